// round 3
// baseline (speedup 1.0000x reference)
#include <cuda_runtime.h>
#include <cuda_bf16.h>

// Problem shape (fixed by reference): B=8, N=2048, D=128
#define B_ 8
#define N_ 2048
#define D_ 128

#define BM 64          // j-rows per block tile
#define BK 32          // k (i-dim) chunk for GEMM1
#define CP (2*D_ + 4)  // concat row pitch (floats), padded
#define WP (D_ + 4)    // W-transpose tile pitch (floats), padded

typedef unsigned long long u64;

// scratch for degrees (no cudaMalloc allowed)
__device__ float g_degree[B_ * N_];

// ---- packed f32x2 helpers (FFMA2 — 2 fp32 MACs per issue on sm_103a) ----
__device__ __forceinline__ u64 pk2(float x, float y) {
    u64 r; asm("mov.b64 %0,{%1,%2};" : "=l"(r) : "f"(x), "f"(y)); return r;
}
__device__ __forceinline__ float2 upk2(u64 v) {
    float2 f; asm("mov.b64 {%0,%1},%2;" : "=f"(f.x), "=f"(f.y) : "l"(v)); return f;
}
__device__ __forceinline__ u64 ffma2(u64 a, u64 b, u64 c) {
    u64 d; asm("fma.rn.f32x2 %0,%1,%2,%3;" : "=l"(d) : "l"(a), "l"(b), "l"(c)); return d;
}

// ---------------------------------------------------------------------------
// Kernel 1: degree[b,j] = sum_i adj[b,j,i]   (one warp per row)
// ---------------------------------------------------------------------------
__global__ void degree_kernel(const float* __restrict__ adj) {
    int warp = (blockIdx.x * blockDim.x + threadIdx.x) >> 5;
    int lane = threadIdx.x & 31;
    if (warp >= B_ * N_) return;
    const float4* row = reinterpret_cast<const float4*>(adj + (size_t)warp * N_);
    float s = 0.f;
    #pragma unroll
    for (int t = 0; t < (N_ / 4) / 32; t++) {
        float4 v = row[t * 32 + lane];
        s += (v.x + v.y) + (v.z + v.w);
    }
    #pragma unroll
    for (int o = 16; o; o >>= 1) s += __shfl_xor_sync(0xffffffffu, s, o);
    if (lane == 0) g_degree[warp] = s;
}

// ---------------------------------------------------------------------------
// Kernel 2: fused  SN = cost^T @ E / deg ;  out = relu([E|SN] @ W^T + bias)
// Block: 256 threads, tile = 64 rows (j) x 128 cols (d). Thread = 8x4 microtile
// computed as packed f32x2 pairs over the row dimension (stage 1) and the
// column dimension (stage 2).
// ---------------------------------------------------------------------------
__global__ void __launch_bounds__(256, 2)
fused_kernel(const float* __restrict__ E,
             const float* __restrict__ cost,
             const float* __restrict__ W,
             const float* __restrict__ bias,
             float* __restrict__ out) {
    extern __shared__ float smem[];
    // stage-1 layout (front of smem)
    float* sCost = smem;              // [BK][BM]
    float* sE    = smem + BK * BM;    // [BK][D_]
    // stage-2 layout (reuses whole smem after sync)
    float* sConcat = smem;            // [BM][CP]
    float* sWt     = smem + BM * CP;  // [64][WP]  (k-major, transposed W chunk)

    const int b     = blockIdx.y;
    const int jBase = blockIdx.x * BM;
    const int tid   = threadIdx.x;
    const int tc    = tid & 31;
    const int tr    = tid >> 5;

    const float* Eb = E    + (size_t)b * N_ * D_;
    const float* Cb = cost + (size_t)b * N_ * N_;

    // accp[c][rp]: packed pair of rows (2rp, 2rp+1) for output column c
    u64 accp[4][4];
    {
        u64 z = pk2(0.f, 0.f);
        #pragma unroll
        for (int c = 0; c < 4; c++)
            #pragma unroll
            for (int rp = 0; rp < 4; rp++) accp[c][rp] = z;
    }

    // ---- Stage 1: SN-tile = cost^T @ E over K = N_ ----
    for (int k0 = 0; k0 < N_; k0 += BK) {
        // cost tile [BK][BM]: coalesced float4 along j
        #pragma unroll
        for (int it = 0; it < (BK * BM / 4) / 256; it++) {
            int f  = it * 256 + tid;          // 0..511
            int i  = f >> 4;                  // 0..31
            int j4 = f & 15;                  // 0..15
            float4 v = *reinterpret_cast<const float4*>(
                Cb + (size_t)(k0 + i) * N_ + jBase + j4 * 4);
            *reinterpret_cast<float4*>(sCost + i * BM + j4 * 4) = v;
        }
        // E tile [BK][D_]
        #pragma unroll
        for (int it = 0; it < (BK * D_ / 4) / 256; it++) {
            int f  = it * 256 + tid;          // 0..1023
            int i  = f >> 5;                  // 0..31
            int d4 = f & 31;                  // 0..31
            float4 v = *reinterpret_cast<const float4*>(
                Eb + (size_t)(k0 + i) * D_ + d4 * 4);
            *reinterpret_cast<float4*>(sE + i * D_ + d4 * 4) = v;
        }
        __syncthreads();
        #pragma unroll
        for (int kk = 0; kk < BK; kk++) {
            float4 bv = *reinterpret_cast<const float4*>(sE + kk * D_ + tc * 4);
            u64 bx = pk2(bv.x, bv.x);
            u64 by = pk2(bv.y, bv.y);
            u64 bz = pk2(bv.z, bv.z);
            u64 bw = pk2(bv.w, bv.w);
            // row pairs come packed straight out of shared (uniform -> broadcast)
            const u64* ap = reinterpret_cast<const u64*>(sCost + kk * BM + tr * 8);
            #pragma unroll
            for (int rp = 0; rp < 4; rp++) {
                u64 a = ap[rp];
                accp[0][rp] = ffma2(a, bx, accp[0][rp]);
                accp[1][rp] = ffma2(a, by, accp[1][rp]);
                accp[2][rp] = ffma2(a, bz, accp[2][rp]);
                accp[3][rp] = ffma2(a, bw, accp[3][rp]);
            }
        }
        __syncthreads();
    }

    // ---- Stage 2 prep: write SN/deg into concat smem, load E rows ----
    #pragma unroll
    for (int rp = 0; rp < 4; rp++) {
        int row0 = tr * 8 + 2 * rp;
        float rd0 = 1.0f / g_degree[b * N_ + jBase + row0];
        float rd1 = 1.0f / g_degree[b * N_ + jBase + row0 + 1];
        float2 a0 = upk2(accp[0][rp]);
        float2 a1 = upk2(accp[1][rp]);
        float2 a2 = upk2(accp[2][rp]);
        float2 a3 = upk2(accp[3][rp]);
        *reinterpret_cast<float4*>(sConcat + row0 * CP + D_ + tc * 4) =
            make_float4(a0.x * rd0, a1.x * rd0, a2.x * rd0, a3.x * rd0);
        *reinterpret_cast<float4*>(sConcat + (row0 + 1) * CP + D_ + tc * 4) =
            make_float4(a0.y * rd1, a1.y * rd1, a2.y * rd1, a3.y * rd1);
    }
    #pragma unroll
    for (int it = 0; it < (BM * D_ / 4) / 256; it++) {
        int f   = it * 256 + tid;   // 0..2047
        int row = f >> 5;
        int d4  = f & 31;
        float4 v = *reinterpret_cast<const float4*>(
            Eb + (size_t)(jBase + row) * D_ + d4 * 4);
        *reinterpret_cast<float4*>(sConcat + row * CP + d4 * 4) = v;
    }

    // acc2[r][cp]: packed column pairs (c0,c1) and (c2,c3), init with bias
    u64 acc2[8][2];
    {
        u64 b01 = *reinterpret_cast<const u64*>(bias + tc * 4);
        u64 b23 = *reinterpret_cast<const u64*>(bias + tc * 4 + 2);
        #pragma unroll
        for (int r = 0; r < 8; r++) { acc2[r][0] = b01; acc2[r][1] = b23; }
    }

    // ---- Stage 2: out-tile = concat @ W^T, K = 2D = 256 in chunks of 64 ----
    for (int kc = 0; kc < 2 * D_; kc += 64) {
        __syncthreads();  // concat writes visible / protect sWt reuse
        #pragma unroll
        for (int it = 0; it < (64 * D_) / 256; it++) {
            int f = it * 256 + tid;
            int d = f >> 6;          // 0..127
            int k = f & 63;          // 0..63, coalesced along k
            sWt[k * WP + d] = W[d * (2 * D_) + kc + k];
        }
        __syncthreads();
        #pragma unroll
        for (int k = 0; k < 64; k++) {
            u64 w01 = *reinterpret_cast<const u64*>(sWt + k * WP + tc * 4);
            u64 w23 = *reinterpret_cast<const u64*>(sWt + k * WP + tc * 4 + 2);
            #pragma unroll
            for (int r = 0; r < 8; r++) {
                float cv = sConcat[(tr * 8 + r) * CP + kc + k];  // broadcast
                u64 cd = pk2(cv, cv);
                acc2[r][0] = ffma2(cd, w01, acc2[r][0]);
                acc2[r][1] = ffma2(cd, w23, acc2[r][1]);
            }
        }
    }

    // ---- epilogue: relu + store ----
    float* Ob = out + (size_t)b * N_ * D_;
    #pragma unroll
    for (int r = 0; r < 8; r++) {
        int row = jBase + tr * 8 + r;
        float2 v01 = upk2(acc2[r][0]);
        float2 v23 = upk2(acc2[r][1]);
        float4 v;
        v.x = fmaxf(v01.x, 0.f);
        v.y = fmaxf(v01.y, 0.f);
        v.z = fmaxf(v23.x, 0.f);
        v.w = fmaxf(v23.y, 0.f);
        *reinterpret_cast<float4*>(Ob + (size_t)row * D_ + tc * 4) = v;
    }
}

// ---------------------------------------------------------------------------
extern "C" void kernel_launch(void* const* d_in, const int* in_sizes, int n_in,
                              void* d_out, int out_size) {
    const float* E    = (const float*)d_in[0];  // embeddings  (B,N,D)
    const float* adj  = (const float*)d_in[1];  // adjacency   (B,N,N)
    const float* cost = (const float*)d_in[2];  // cost        (B,N,N)
    const float* W    = (const float*)d_in[3];  // (D, 2D)
    const float* bias = (const float*)d_in[4];  // (D,)
    float* out = (float*)d_out;

    // degree: one warp per row, 8 rows per 256-thread block
    {
        int rows = B_ * N_;
        int blocks = (rows * 32 + 255) / 256;
        degree_kernel<<<blocks, 256>>>(adj);
    }

    // fused main kernel
    {
        size_t smem = (size_t)(BM * CP + 64 * WP) * sizeof(float);  // ~100 KB
        cudaFuncSetAttribute(fused_kernel,
                             cudaFuncAttributeMaxDynamicSharedMemorySize,
                             (int)smem);
        dim3 grid(N_ / BM, B_);
        fused_kernel<<<grid, 256, smem>>>(E, cost, W, bias, out);
    }
}

// round 5
// speedup vs baseline: 1.9618x; 1.9618x over previous
#include <cuda_runtime.h>
#include <cuda_bf16.h>
#include <cstdint>

#define B_ 8
#define N_ 2048
#define D_ 128
#define KC 64
#define NCH1 32

#define TILE_B 16384
#define SM_TILES 1024
#define SMEM_TOTAL (SM_TILES + 2 * 4 * TILE_B)   // 132 KB

#define SWZ(x) ((x) ^ (((x) >> 3) & 0x70))

__device__ __forceinline__ uint32_t smem_u32(const void* p) {
    uint32_t a;
    asm("{ .reg .u64 t; cvta.to.shared.u64 t, %1; cvt.u32.u64 %0, t; }"
        : "=r"(a) : "l"(p));
    return a;
}

// split fp32 into bf16 hi + bf16 lo (lo = round(x - hi)); pack pairs
__device__ __forceinline__ void split2(float x0, float x1,
                                       uint32_t& hi, uint32_t& lo) {
    __nv_bfloat16 h0 = __float2bfloat16_rn(x0);
    __nv_bfloat16 h1 = __float2bfloat16_rn(x1);
    __nv_bfloat162 H, L;
    H.x = h0; H.y = h1;
    L.x = __float2bfloat16_rn(x0 - __bfloat162float(h0));
    L.y = __float2bfloat16_rn(x1 - __bfloat162float(h1));
    hi = *reinterpret_cast<uint32_t*>(&H);
    lo = *reinterpret_cast<uint32_t*>(&L);
}

__device__ __forceinline__ void ldsm4(uint32_t addr, uint32_t r[4]) {
    asm volatile("ldmatrix.sync.aligned.m8n8.x4.shared.b16 {%0,%1,%2,%3}, [%4];"
                 : "=r"(r[0]), "=r"(r[1]), "=r"(r[2]), "=r"(r[3]) : "r"(addr));
}

__device__ __forceinline__ void mma16816(float c[4],
                                         const uint32_t a[4],
                                         uint32_t b0, uint32_t b1) {
    asm volatile(
        "mma.sync.aligned.m16n8k16.row.col.f32.bf16.bf16.f32 "
        "{%0,%1,%2,%3}, {%4,%5,%6,%7}, {%8,%9}, {%0,%1,%2,%3};"
        : "+f"(c[0]), "+f"(c[1]), "+f"(c[2]), "+f"(c[3])
        : "r"(a[0]), "r"(a[1]), "r"(a[2]), "r"(a[3]), "r"(b0), "r"(b1));
}

// One 128x128x64 chunk: 3-pass bf16-split MMA from SW128 tiles.
// Tile layout at buf: [AH][AL][BH][BL], each 128 rows x 128B (64 bf16).
__device__ __forceinline__ void mma_chunk(uint32_t buf, int m0, int n0,
                                          int lane, float (&acc)[2][4][4]) {
    const int lr = lane & 15;
    const int kh = (lane >> 4) * 16;   // byte offset of k-half
    #pragma unroll
    for (int ks = 0; ks < 4; ks++) {
        uint32_t ah[2][4], al[2][4], bh[2][4], bl[2][4];
        #pragma unroll
        for (int mt = 0; mt < 2; mt++) {
            int row = m0 + mt * 16 + lr;
            uint32_t off = row * 128 + ((ks * 32 + kh) ^ ((row & 7) << 4));
            ldsm4(buf + off, ah[mt]);
            ldsm4(buf + TILE_B + off, al[mt]);
        }
        #pragma unroll
        for (int nt2 = 0; nt2 < 2; nt2++) {
            int row = n0 + nt2 * 16 + lr;
            uint32_t off = row * 128 + ((ks * 32 + kh) ^ ((row & 7) << 4));
            ldsm4(buf + 2 * TILE_B + off, bh[nt2]);
            ldsm4(buf + 3 * TILE_B + off, bl[nt2]);
        }
        #pragma unroll
        for (int mt = 0; mt < 2; mt++)
            #pragma unroll
            for (int nt = 0; nt < 4; nt++) {
                int n2 = nt >> 1, sel = nt & 1;
                mma16816(acc[mt][nt], ah[mt], bh[n2][sel], bh[n2][sel + 2]);
                mma16816(acc[mt][nt], ah[mt], bl[n2][sel], bl[n2][sel + 2]);
                mma16816(acc[mt][nt], al[mt], bh[n2][sel], bh[n2][sel + 2]);
            }
    }
}

__global__ void __launch_bounds__(512, 1)
fused(const float* __restrict__ E, const float* __restrict__ adj,
      const float* __restrict__ cost, const float* __restrict__ W,
      const float* __restrict__ bias, float* __restrict__ out) {
    extern __shared__ char smem[];
    const uint32_t sb = smem_u32(smem);
    float* sDeg = reinterpret_cast<float*>(smem);   // 128 floats

    const int tid = threadIdx.x, w = tid >> 5, l = tid & 31;
    const int wm = w >> 2, wn = w & 3;
    const int m0 = wm * 32, n0 = wn * 32;
    const int b = blockIdx.y, jBase = blockIdx.x * 128;

    const float* Cb = cost + (size_t)b * N_ * N_ + jBase;   // [i][jBase+j]
    const float* Eb = E + (size_t)b * N_ * D_;              // [i][d]
    const float* Ab = adj + (size_t)b * N_ * N_ + (size_t)jBase * N_;

    // loader indices
    const int jA  = wn * 32 + l;   // j (A tile) / d (B tile) row
    const int ipb = wm * 8;        // i-pair block
    const int jD  = w * 8;         // degree row base (+ t*2 + (l>>4))

    float acc[2][4][4];
    #pragma unroll
    for (int mt = 0; mt < 2; mt++)
        #pragma unroll
        for (int nt = 0; nt < 4; nt++)
            #pragma unroll
            for (int q = 0; q < 4; q++) acc[mt][nt][q] = 0.f;

    float dacc[4] = {0.f, 0.f, 0.f, 0.f};
    float pa0[8], pa1[8], pb0[8], pb1[8];
    float4 pd[4];

    // prefetch chunk 0
    #pragma unroll
    for (int it = 0; it < 8; it++) {
        const float* p = Cb + (size_t)(2 * (ipb + it)) * N_ + jA;
        pa0[it] = p[0]; pa1[it] = p[N_];
        const float* q = Eb + (size_t)(2 * (ipb + it)) * D_ + jA;
        pb0[it] = q[0]; pb1[it] = q[D_];
    }
    #pragma unroll
    for (int t = 0; t < 4; t++)
        pd[t] = *reinterpret_cast<const float4*>(
            Ab + (size_t)(jD + t * 2 + (l >> 4)) * N_ + (l & 15) * 4);

    // ================= Stage 1: SN-pre = cost^T @ E  (K = 2048) ============
    for (int c = 0; c < NCH1; c++) {
        const int p = c & 1;
        char* bufc = smem + SM_TILES + p * (4 * TILE_B);
        const uint32_t bufb = sb + SM_TILES + p * (4 * TILE_B);

        // convert + STS prefetched chunk
        #pragma unroll
        for (int it = 0; it < 8; it += 2) {
            uint32_t h0, l0, h1, l1;
            uint32_t off = SWZ(jA * 128 + (ipb + it) * 4);
            split2(pa0[it], pa1[it], h0, l0);
            split2(pa0[it + 1], pa1[it + 1], h1, l1);
            *reinterpret_cast<uint2*>(bufc + off)          = make_uint2(h0, h1);
            *reinterpret_cast<uint2*>(bufc + TILE_B + off) = make_uint2(l0, l1);
            split2(pb0[it], pb1[it], h0, l0);
            split2(pb0[it + 1], pb1[it + 1], h1, l1);
            *reinterpret_cast<uint2*>(bufc + 2 * TILE_B + off) = make_uint2(h0, h1);
            *reinterpret_cast<uint2*>(bufc + 3 * TILE_B + off) = make_uint2(l0, l1);
        }
        #pragma unroll
        for (int t = 0; t < 4; t++)
            dacc[t] += (pd[t].x + pd[t].y) + (pd[t].z + pd[t].w);

        if (c == NCH1 - 1) {   // finalize degrees
            #pragma unroll
            for (int t = 0; t < 4; t++) {
                float s = dacc[t];
                s += __shfl_xor_sync(~0u, s, 1);
                s += __shfl_xor_sync(~0u, s, 2);
                s += __shfl_xor_sync(~0u, s, 4);
                s += __shfl_xor_sync(~0u, s, 8);
                if ((l & 15) == 0) sDeg[jD + t * 2 + (l >> 4)] = s;
            }
        }
        __syncthreads();

        if (c + 1 < NCH1) {   // prefetch next chunk
            const int k0 = (c + 1) * KC;
            #pragma unroll
            for (int it = 0; it < 8; it++) {
                const float* p2 = Cb + (size_t)(k0 + 2 * (ipb + it)) * N_ + jA;
                pa0[it] = p2[0]; pa1[it] = p2[N_];
                const float* q2 = Eb + (size_t)(k0 + 2 * (ipb + it)) * D_ + jA;
                pb0[it] = q2[0]; pb1[it] = q2[D_];
            }
            #pragma unroll
            for (int t = 0; t < 4; t++)
                pd[t] = *reinterpret_cast<const float4*>(
                    Ab + (size_t)(jD + t * 2 + (l >> 4)) * N_ + k0 + (l & 15) * 4);
        }
        mma_chunk(bufb, m0, n0, l, acc);
    }

    // ================= Stage 2: out = relu([E|SN] @ W^T + b)  (K = 256) =====
    float acc2[2][4][4];
    #pragma unroll
    for (int mt = 0; mt < 2; mt++)
        #pragma unroll
        for (int nt = 0; nt < 4; nt++)
            #pragma unroll
            for (int q = 0; q < 4; q++) acc2[mt][nt][q] = 0.f;

    for (int c = NCH1; c < NCH1 + 4; c++) {
        const int p = c & 1;
        char* bufc = smem + SM_TILES + p * (4 * TILE_B);
        const uint32_t bufb = sb + SM_TILES + p * (4 * TILE_B);
        const int cs = c - NCH1;
        const int s = (cs < 2) ? cs + 2 : cs - 2;   // order: 2,3,0,1 (SN first)

        // B2 = W[:, 64s .. 64s+64)
        #pragma unroll
        for (int q2 = 0; q2 < 4; q2++) {
            int idx = q2 * 512 + tid;
            int row = idx >> 4, g = idx & 15;
            float4 v = *reinterpret_cast<const float4*>(
                W + row * (2 * D_) + s * 64 + g * 4);
            uint32_t h0, l0, h1, l1;
            split2(v.x, v.y, h0, l0);
            split2(v.z, v.w, h1, l1);
            uint32_t off = SWZ(row * 128 + g * 8);
            *reinterpret_cast<uint2*>(bufc + 2 * TILE_B + off) = make_uint2(h0, h1);
            *reinterpret_cast<uint2*>(bufc + 3 * TILE_B + off) = make_uint2(l0, l1);
        }

        if (s >= 2) {
            // A2 = SN columns 64(s-2)..+64, sourced from stage-1 accumulators
            if ((wn >> 1) == (s - 2)) {
                #pragma unroll
                for (int mt = 0; mt < 2; mt++) {
                    int r0 = m0 + mt * 16 + (l >> 2);
                    float rd0 = 1.0f / sDeg[r0];
                    float rd1 = 1.0f / sDeg[r0 + 8];
                    #pragma unroll
                    for (int nt = 0; nt < 4; nt++) {
                        int k = (wn & 1) * 32 + nt * 8 + (l & 3) * 2;
                        uint32_t h, lo;
                        split2(acc[mt][nt][0] * rd0, acc[mt][nt][1] * rd0, h, lo);
                        uint32_t off = SWZ(r0 * 128 + k * 2);
                        *reinterpret_cast<uint32_t*>(bufc + off) = h;
                        *reinterpret_cast<uint32_t*>(bufc + TILE_B + off) = lo;
                        split2(acc[mt][nt][2] * rd1, acc[mt][nt][3] * rd1, h, lo);
                        off = SWZ((r0 + 8) * 128 + k * 2);
                        *reinterpret_cast<uint32_t*>(bufc + off) = h;
                        *reinterpret_cast<uint32_t*>(bufc + TILE_B + off) = lo;
                    }
                }
            }
        } else {
            // A2 = E rows jBase.., columns 64s..+64 (k-contiguous)
            #pragma unroll
            for (int q2 = 0; q2 < 4; q2++) {
                int idx = q2 * 512 + tid;
                int row = idx >> 4, g = idx & 15;
                float4 v = *reinterpret_cast<const float4*>(
                    Eb + (size_t)(jBase + row) * D_ + s * 64 + g * 4);
                uint32_t h0, l0, h1, l1;
                split2(v.x, v.y, h0, l0);
                split2(v.z, v.w, h1, l1);
                uint32_t off = SWZ(row * 128 + g * 8);
                *reinterpret_cast<uint2*>(bufc + off) = make_uint2(h0, h1);
                *reinterpret_cast<uint2*>(bufc + TILE_B + off) = make_uint2(l0, l1);
            }
        }
        __syncthreads();
        mma_chunk(bufb, m0, n0, l, acc2);
    }

    // ---- epilogue: bias + relu + store ----
    #pragma unroll
    for (int mt = 0; mt < 2; mt++)
        #pragma unroll
        for (int nt = 0; nt < 4; nt++) {
            int col = n0 + nt * 8 + (l & 3) * 2;
            float2 bv = *reinterpret_cast<const float2*>(bias + col);
            int r0 = jBase + m0 + mt * 16 + (l >> 2);
            float2 o0, o1;
            o0.x = fmaxf(acc2[mt][nt][0] + bv.x, 0.f);
            o0.y = fmaxf(acc2[mt][nt][1] + bv.y, 0.f);
            o1.x = fmaxf(acc2[mt][nt][2] + bv.x, 0.f);
            o1.y = fmaxf(acc2[mt][nt][3] + bv.y, 0.f);
            *reinterpret_cast<float2*>(
                out + (size_t)b * N_ * D_ + (size_t)r0 * D_ + col) = o0;
            *reinterpret_cast<float2*>(
                out + (size_t)b * N_ * D_ + (size_t)(r0 + 8) * D_ + col) = o1;
        }
}

// ---------------------------------------------------------------------------
extern "C" void kernel_launch(void* const* d_in, const int* in_sizes, int n_in,
                              void* d_out, int out_size) {
    const float* E    = (const float*)d_in[0];
    const float* adj  = (const float*)d_in[1];
    const float* cost = (const float*)d_in[2];
    const float* W    = (const float*)d_in[3];
    const float* bias = (const float*)d_in[4];
    float* out = (float*)d_out;

    cudaFuncSetAttribute(fused, cudaFuncAttributeMaxDynamicSharedMemorySize,
                         SMEM_TOTAL);
    dim3 grid(N_ / 128, B_);
    fused<<<grid, 512, SMEM_TOTAL>>>(E, adj, cost, W, bias, out);
}

// round 6
// speedup vs baseline: 2.0279x; 1.0337x over previous
#include <cuda_runtime.h>
#include <cuda_bf16.h>
#include <cstdint>

#define B_ 8
#define N_ 2048
#define D_ 128
#define KC 64
#define NCH1 32

#define TILE_B 16384
#define TILE4  (4 * TILE_B)
#define SM_TILES 1024
#define NBUF 3
#define SMEM_TOTAL (SM_TILES + NBUF * TILE4)   // 1K + 192K

#define SWZ(x) ((x) ^ (((x) >> 3) & 0x70))

__device__ __forceinline__ uint32_t smem_u32(const void* p) {
    uint32_t a;
    asm("{ .reg .u64 t; cvta.to.shared.u64 t, %1; cvt.u32.u64 %0, t; }"
        : "=r"(a) : "l"(p));
    return a;
}

// split fp32 pair into packed bf16 hi + bf16 lo (lo = rn(x - hi))
__device__ __forceinline__ void split2(float x0, float x1,
                                       uint32_t& hi, uint32_t& lo) {
    uint32_t H;
    asm("cvt.rn.bf16x2.f32 %0, %1, %2;" : "=r"(H) : "f"(x1), "f"(x0));
    float h0 = __uint_as_float(H << 16);
    float h1 = __uint_as_float(H & 0xFFFF0000u);
    uint32_t L;
    asm("cvt.rn.bf16x2.f32 %0, %1, %2;" : "=r"(L)
        : "f"(x1 - h1), "f"(x0 - h0));
    hi = H; lo = L;
}

__device__ __forceinline__ void ldsm4(uint32_t addr, uint32_t r[4]) {
    asm volatile("ldmatrix.sync.aligned.m8n8.x4.shared.b16 {%0,%1,%2,%3}, [%4];"
                 : "=r"(r[0]), "=r"(r[1]), "=r"(r[2]), "=r"(r[3]) : "r"(addr));
}

__device__ __forceinline__ void mma16816(float c[4],
                                         const uint32_t a[4],
                                         uint32_t b0, uint32_t b1) {
    asm volatile(
        "mma.sync.aligned.m16n8k16.row.col.f32.bf16.bf16.f32 "
        "{%0,%1,%2,%3}, {%4,%5,%6,%7}, {%8,%9}, {%0,%1,%2,%3};"
        : "+f"(c[0]), "+f"(c[1]), "+f"(c[2]), "+f"(c[3])
        : "r"(a[0]), "r"(a[1]), "r"(a[2]), "r"(a[3]), "r"(b0), "r"(b1));
}

// One ks-slice (k = 16) of the 128x128 MMA: LDSM + 3-pass split MMAs,
// ordered pass-outer so accumulator reuse is 8 HMMAs apart.
__device__ __forceinline__ void mma_slice(uint32_t bufR, int ks, int m0, int n0,
                                          int lane, float (&acc)[2][4][4]) {
    const int lr = lane & 15;
    const int kh = (lane >> 4) * 16;
    uint32_t ah[2][4], al[2][4], bh[2][4], bl[2][4];
    #pragma unroll
    for (int mt = 0; mt < 2; mt++) {
        int row = m0 + mt * 16 + lr;
        uint32_t off = row * 128 + ((ks * 32 + kh) ^ ((row & 7) << 4));
        ldsm4(bufR + off, ah[mt]);
        ldsm4(bufR + TILE_B + off, al[mt]);
    }
    #pragma unroll
    for (int nt2 = 0; nt2 < 2; nt2++) {
        int row = n0 + nt2 * 16 + lr;
        uint32_t off = row * 128 + ((ks * 32 + kh) ^ ((row & 7) << 4));
        ldsm4(bufR + 2 * TILE_B + off, bh[nt2]);
        ldsm4(bufR + 3 * TILE_B + off, bl[nt2]);
    }
    #pragma unroll
    for (int ps = 0; ps < 3; ps++) {
        #pragma unroll
        for (int mt = 0; mt < 2; mt++)
            #pragma unroll
            for (int nt = 0; nt < 4; nt++) {
                int n2 = nt >> 1, sel = nt & 1;
                const uint32_t* A = (ps == 2) ? al[mt] : ah[mt];
                const uint32_t* Bf = (ps == 1) ? bl[n2] : bh[n2];
                mma16816(acc[mt][nt], A, Bf[sel], Bf[sel + 2]);
            }
    }
}

__global__ void __launch_bounds__(512, 1)
fused(const float* __restrict__ E, const float* __restrict__ adj,
      const float* __restrict__ cost, const float* __restrict__ W,
      const float* __restrict__ bias, float* __restrict__ out) {
    extern __shared__ char smem[];
    const uint32_t sb = smem_u32(smem);
    float* sDeg = reinterpret_cast<float*>(smem);   // 128 floats

    const int tid = threadIdx.x, w = tid >> 5, l = tid & 31;
    const int wm = w >> 2, wn = w & 3;
    const int m0 = wm * 32, n0 = wn * 32;
    const int b = blockIdx.y, jBase = blockIdx.x * 128;

    const float* Cb = cost + (size_t)b * N_ * N_ + jBase;
    const float* Eb = E + (size_t)b * N_ * D_;
    const float* Ab = adj + (size_t)b * N_ * N_ + (size_t)jBase * N_;

    const int jA  = wn * 32 + l;
    const int ipb = wm * 8;
    const int jD  = w * 8;
    const int dRow = jD + (l >> 4);          // + 2*g
    const int dCol = (l & 15) * 4;

    float acc[2][4][4];
    #pragma unroll
    for (int mt = 0; mt < 2; mt++)
        #pragma unroll
        for (int nt = 0; nt < 4; nt++)
            #pragma unroll
            for (int q = 0; q < 4; q++) acc[mt][nt][q] = 0.f;

    float dacc[4] = {0.f, 0.f, 0.f, 0.f};
    float pa0[8], pa1[8], pb0[8], pb1[8];
    float4 pd[4];

    // ---- prologue: LDG chunk0, convert+STS chunk0 -> buf0, adj0, LDG chunk1
    #pragma unroll
    for (int it = 0; it < 8; it++) {
        const float* p = Cb + (size_t)(2 * (ipb + it)) * N_ + jA;
        pa0[it] = p[0]; pa1[it] = p[N_];
        const float* q = Eb + (size_t)(2 * (ipb + it)) * D_ + jA;
        pb0[it] = q[0]; pb1[it] = q[D_];
    }
    #pragma unroll
    for (int g = 0; g < 4; g++)
        pd[g] = *reinterpret_cast<const float4*>(
            Ab + (size_t)(dRow + 2 * g) * N_ + dCol);
    {
        char* bufW = smem + SM_TILES;   // buf 0
        #pragma unroll
        for (int g = 0; g < 4; g++) {
            int it = 2 * g;
            uint32_t h0, l0, h1, l1;
            uint32_t off = SWZ(jA * 128 + (ipb + it) * 4);
            split2(pa0[it], pa1[it], h0, l0);
            split2(pa0[it + 1], pa1[it + 1], h1, l1);
            *reinterpret_cast<uint2*>(bufW + off)          = make_uint2(h0, h1);
            *reinterpret_cast<uint2*>(bufW + TILE_B + off) = make_uint2(l0, l1);
            split2(pb0[it], pb1[it], h0, l0);
            split2(pb0[it + 1], pb1[it + 1], h1, l1);
            *reinterpret_cast<uint2*>(bufW + 2 * TILE_B + off) = make_uint2(h0, h1);
            *reinterpret_cast<uint2*>(bufW + 3 * TILE_B + off) = make_uint2(l0, l1);
            dacc[g] += (pd[g].x + pd[g].y) + (pd[g].z + pd[g].w);
        }
        #pragma unroll
        for (int it = 0; it < 8; it++) {
            const float* p = Cb + (size_t)(KC + 2 * (ipb + it)) * N_ + jA;
            pa0[it] = p[0]; pa1[it] = p[N_];
            const float* q = Eb + (size_t)(KC + 2 * (ipb + it)) * D_ + jA;
            pb0[it] = q[0]; pb1[it] = q[D_];
        }
        #pragma unroll
        for (int g = 0; g < 4; g++)
            pd[g] = *reinterpret_cast<const float4*>(
                Ab + (size_t)(dRow + 2 * g) * N_ + KC + dCol);
    }
    __syncthreads();

    // ================= Stage 1 fused mainloop =================
    // invariant at iter c: buf c%3 holds chunk c; regs hold chunk c+1
    for (int c = 0; c < NCH1; c++) {
        const uint32_t bufR = sb + SM_TILES + (c % 3) * TILE4;
        char* bufW = smem + SM_TILES + ((c + 1) % 3) * TILE4;
        const bool doConv = (c + 1 < NCH1);
        const bool doLdg  = (c + 2 < NCH1);
        const int k0n = (c + 2) * KC;

        #pragma unroll
        for (int ks = 0; ks < 4; ks++) {
            mma_slice(bufR, ks, m0, n0, l, acc);
            if (doConv) {
                int it = 2 * ks;
                uint32_t h0, l0, h1, l1;
                uint32_t off = SWZ(jA * 128 + (ipb + it) * 4);
                split2(pa0[it], pa1[it], h0, l0);
                split2(pa0[it + 1], pa1[it + 1], h1, l1);
                *reinterpret_cast<uint2*>(bufW + off)          = make_uint2(h0, h1);
                *reinterpret_cast<uint2*>(bufW + TILE_B + off) = make_uint2(l0, l1);
                split2(pb0[it], pb1[it], h0, l0);
                split2(pb0[it + 1], pb1[it + 1], h1, l1);
                *reinterpret_cast<uint2*>(bufW + 2 * TILE_B + off) = make_uint2(h0, h1);
                *reinterpret_cast<uint2*>(bufW + 3 * TILE_B + off) = make_uint2(l0, l1);
                dacc[ks] += (pd[ks].x + pd[ks].y) + (pd[ks].z + pd[ks].w);
            }
            if (doLdg) {
                int it = 2 * ks;
                const float* p = Cb + (size_t)(k0n + 2 * (ipb + it)) * N_ + jA;
                pa0[it] = p[0]; pa1[it] = p[N_];
                const float* p2 = Cb + (size_t)(k0n + 2 * (ipb + it + 1)) * N_ + jA;
                pa0[it + 1] = p2[0]; pa1[it + 1] = p2[N_];
                const float* q = Eb + (size_t)(k0n + 2 * (ipb + it)) * D_ + jA;
                pb0[it] = q[0]; pb1[it] = q[D_];
                const float* q2 = Eb + (size_t)(k0n + 2 * (ipb + it + 1)) * D_ + jA;
                pb0[it + 1] = q2[0]; pb1[it + 1] = q2[D_];
                pd[ks] = *reinterpret_cast<const float4*>(
                    Ab + (size_t)(dRow + 2 * ks) * N_ + k0n + dCol);
            }
        }
        __syncthreads();
    }

    // ---- degrees -> smem ----
    #pragma unroll
    for (int t = 0; t < 4; t++) {
        float s = dacc[t];
        s += __shfl_xor_sync(~0u, s, 1);
        s += __shfl_xor_sync(~0u, s, 2);
        s += __shfl_xor_sync(~0u, s, 4);
        s += __shfl_xor_sync(~0u, s, 8);
        if ((l & 15) == 0) sDeg[dRow + 2 * t] = s;
    }
    __syncthreads();

    // ================= Stage 2: out = relu([E|SN] @ W^T + b) ================
    float acc2[2][4][4];
    #pragma unroll
    for (int mt = 0; mt < 2; mt++)
        #pragma unroll
        for (int nt = 0; nt < 4; nt++)
            #pragma unroll
            for (int q = 0; q < 4; q++) acc2[mt][nt][q] = 0.f;

    for (int cs = 0; cs < 4; cs++) {
        const int p = (NCH1 + cs) % NBUF;
        char* bufc = smem + SM_TILES + p * TILE4;
        const uint32_t bufb = sb + SM_TILES + p * TILE4;
        const int s = (cs < 2) ? cs + 2 : cs - 2;   // SN chunks first

        // B2 = W[:, 64s..64s+64)
        #pragma unroll
        for (int q2 = 0; q2 < 4; q2++) {
            int idx = q2 * 512 + tid;
            int row = idx >> 4, g = idx & 15;
            float4 v = *reinterpret_cast<const float4*>(
                W + row * (2 * D_) + s * 64 + g * 4);
            uint32_t h0, l0, h1, l1;
            split2(v.x, v.y, h0, l0);
            split2(v.z, v.w, h1, l1);
            uint32_t off = SWZ(row * 128 + g * 8);
            *reinterpret_cast<uint2*>(bufc + 2 * TILE_B + off) = make_uint2(h0, h1);
            *reinterpret_cast<uint2*>(bufc + 3 * TILE_B + off) = make_uint2(l0, l1);
        }

        if (s >= 2) {
            // A2 = SN columns 64(s-2)..+64 from stage-1 accumulators
            if ((wn >> 1) == (s - 2)) {
                #pragma unroll
                for (int mt = 0; mt < 2; mt++) {
                    int r0 = m0 + mt * 16 + (l >> 2);
                    float rd0 = 1.0f / sDeg[r0];
                    float rd1 = 1.0f / sDeg[r0 + 8];
                    #pragma unroll
                    for (int nt = 0; nt < 4; nt++) {
                        int k = (wn & 1) * 32 + nt * 8 + (l & 3) * 2;
                        uint32_t h, lo;
                        split2(acc[mt][nt][0] * rd0, acc[mt][nt][1] * rd0, h, lo);
                        uint32_t off = SWZ(r0 * 128 + k * 2);
                        *reinterpret_cast<uint32_t*>(bufc + off) = h;
                        *reinterpret_cast<uint32_t*>(bufc + TILE_B + off) = lo;
                        split2(acc[mt][nt][2] * rd1, acc[mt][nt][3] * rd1, h, lo);
                        off = SWZ((r0 + 8) * 128 + k * 2);
                        *reinterpret_cast<uint32_t*>(bufc + off) = h;
                        *reinterpret_cast<uint32_t*>(bufc + TILE_B + off) = lo;
                    }
                }
            }
        } else {
            // A2 = E rows jBase.., columns 64s..+64
            #pragma unroll
            for (int q2 = 0; q2 < 4; q2++) {
                int idx = q2 * 512 + tid;
                int row = idx >> 4, g = idx & 15;
                float4 v = *reinterpret_cast<const float4*>(
                    Eb + (size_t)(jBase + row) * D_ + s * 64 + g * 4);
                uint32_t h0, l0, h1, l1;
                split2(v.x, v.y, h0, l0);
                split2(v.z, v.w, h1, l1);
                uint32_t off = SWZ(row * 128 + g * 8);
                *reinterpret_cast<uint2*>(bufc + off) = make_uint2(h0, h1);
                *reinterpret_cast<uint2*>(bufc + TILE_B + off) = make_uint2(l0, l1);
            }
        }
        __syncthreads();
        #pragma unroll
        for (int ks = 0; ks < 4; ks++)
            mma_slice(bufb, ks, m0, n0, l, acc2);
        __syncthreads();
    }

    // ---- epilogue: bias + relu + store ----
    #pragma unroll
    for (int mt = 0; mt < 2; mt++)
        #pragma unroll
        for (int nt = 0; nt < 4; nt++) {
            int col = n0 + nt * 8 + (l & 3) * 2;
            float2 bv = *reinterpret_cast<const float2*>(bias + col);
            int r0 = jBase + m0 + mt * 16 + (l >> 2);
            float2 o0, o1;
            o0.x = fmaxf(acc2[mt][nt][0] + bv.x, 0.f);
            o0.y = fmaxf(acc2[mt][nt][1] + bv.y, 0.f);
            o1.x = fmaxf(acc2[mt][nt][2] + bv.x, 0.f);
            o1.y = fmaxf(acc2[mt][nt][3] + bv.y, 0.f);
            *reinterpret_cast<float2*>(
                out + (size_t)b * N_ * D_ + (size_t)r0 * D_ + col) = o0;
            *reinterpret_cast<float2*>(
                out + (size_t)b * N_ * D_ + (size_t)(r0 + 8) * D_ + col) = o1;
        }
}

// ---------------------------------------------------------------------------
extern "C" void kernel_launch(void* const* d_in, const int* in_sizes, int n_in,
                              void* d_out, int out_size) {
    const float* E    = (const float*)d_in[0];
    const float* adj  = (const float*)d_in[1];
    const float* cost = (const float*)d_in[2];
    const float* W    = (const float*)d_in[3];
    const float* bias = (const float*)d_in[4];
    float* out = (float*)d_out;

    cudaFuncSetAttribute(fused, cudaFuncAttributeMaxDynamicSharedMemorySize,
                         SMEM_TOTAL);
    dim3 grid(N_ / 128, B_);
    fused<<<grid, 512, SMEM_TOTAL>>>(E, adj, cost, W, bias, out);
}

// round 8
// speedup vs baseline: 2.1969x; 1.0834x over previous
#include <cuda_runtime.h>
#include <cuda_fp16.h>
#include <cstdint>

#define B_ 8
#define N_ 2048
#define D_ 128
#define KC 64
#define NCH1 32

#define TILE_B 16384
#define TILE4  (4 * TILE_B)
#define SM_TILES 1024
#define NBUF 3
#define SMEM_TOTAL (SM_TILES + NBUF * TILE4)   // 1K + 192K

#define SWZ(x) ((x) ^ (((x) >> 3) & 0x70))

// ---- precomputed fp16 splits (device scratch; no cudaMalloc allowed) ----
__device__ __half g_EThi[B_ * D_ * N_];   // E^T  [b][d][i]
__device__ __half g_ETlo[B_ * D_ * N_];
__device__ __half g_ENhi[B_ * N_ * D_];   // E    [b][i][d]
__device__ __half g_ENlo[B_ * N_ * D_];
__device__ __half g_Whi[D_ * 2 * D_];     // W    [dout][k]
__device__ __half g_Wlo[D_ * 2 * D_];

__device__ __forceinline__ uint32_t smem_u32(const void* p) {
    uint32_t a;
    asm("{ .reg .u64 t; cvta.to.shared.u64 t, %1; cvt.u32.u64 %0, t; }"
        : "=r"(a) : "l"(p));
    return a;
}

__device__ __forceinline__ void cpasync16(uint32_t dst, const void* src) {
    asm volatile("cp.async.cg.shared.global [%0], [%1], 16;"
                 :: "r"(dst), "l"(src));
}
#define CP_COMMIT() asm volatile("cp.async.commit_group;" ::: "memory")
#define CP_WAIT0()  asm volatile("cp.async.wait_group 0;" ::: "memory")
#define CP_WAIT1()  asm volatile("cp.async.wait_group 1;" ::: "memory")

// pack 2 floats to fp16x2 (x0 low, x1 high)
__device__ __forceinline__ uint32_t cvth2(float x0, float x1) {
    uint32_t H;
    asm("cvt.rn.f16x2.f32 %0, %1, %2;" : "=r"(H) : "f"(x1), "f"(x0));
    return H;
}
// full split: hi fp16x2 + lo fp16x2
__device__ __forceinline__ void split2h(float x0, float x1,
                                        uint32_t& hi, uint32_t& lo) {
    uint32_t H;
    asm("cvt.rn.f16x2.f32 %0, %1, %2;" : "=r"(H) : "f"(x1), "f"(x0));
    float h0, h1;
    asm("{ .reg .f16 a,b; mov.b32 {a,b}, %2; cvt.f32.f16 %0, a; cvt.f32.f16 %1, b; }"
        : "=f"(h0), "=f"(h1) : "r"(H));
    asm("cvt.rn.f16x2.f32 %0, %1, %2;" : "=r"(lo) : "f"(x1 - h1), "f"(x0 - h0));
    hi = H;
}

__device__ __forceinline__ void ldsm4(uint32_t addr, uint32_t r[4]) {
    asm volatile("ldmatrix.sync.aligned.m8n8.x4.shared.b16 {%0,%1,%2,%3}, [%4];"
                 : "=r"(r[0]), "=r"(r[1]), "=r"(r[2]), "=r"(r[3]) : "r"(addr));
}

__device__ __forceinline__ void mma16816(float c[4],
                                         const uint32_t a[4],
                                         uint32_t b0, uint32_t b1) {
    asm volatile(
        "mma.sync.aligned.m16n8k16.row.col.f32.f16.f16.f32 "
        "{%0,%1,%2,%3}, {%4,%5,%6,%7}, {%8,%9}, {%0,%1,%2,%3};"
        : "+f"(c[0]), "+f"(c[1]), "+f"(c[2]), "+f"(c[3])
        : "r"(a[0]), "r"(a[1]), "r"(a[2]), "r"(a[3]), "r"(b0), "r"(b1));
}

// 2-pass slice (stage 1): acc += Ahi*(Bhi + Blo)
__device__ __forceinline__ void mma2p(uint32_t bufR, int ks, int m0, int n0,
                                      int lane, float (&acc)[2][4][4]) {
    const int lr = lane & 15;
    const int kh = (lane >> 4) * 16;
    uint32_t ah[2][4], bh[2][4], bl[2][4];
    #pragma unroll
    for (int mt = 0; mt < 2; mt++) {
        int row = m0 + mt * 16 + lr;
        uint32_t off = row * 128 + ((ks * 32 + kh) ^ ((row & 7) << 4));
        ldsm4(bufR + off, ah[mt]);
    }
    #pragma unroll
    for (int nt2 = 0; nt2 < 2; nt2++) {
        int row = n0 + nt2 * 16 + lr;
        uint32_t off = row * 128 + ((ks * 32 + kh) ^ ((row & 7) << 4));
        ldsm4(bufR + 2 * TILE_B + off, bh[nt2]);
        ldsm4(bufR + 3 * TILE_B + off, bl[nt2]);
    }
    #pragma unroll
    for (int ps = 0; ps < 2; ps++)
        #pragma unroll
        for (int mt = 0; mt < 2; mt++)
            #pragma unroll
            for (int nt = 0; nt < 4; nt++) {
                int n2 = nt >> 1, sel = nt & 1;
                const uint32_t* Bf = ps ? bl[n2] : bh[n2];
                mma16816(acc[mt][nt], ah[mt], Bf[sel], Bf[sel + 2]);
            }
}

// 3-pass slice (stage 2): acc += Ahi*Bhi + Ahi*Blo + Alo*Bhi
__device__ __forceinline__ void mma3p(uint32_t bufR, int ks, int m0, int n0,
                                      int lane, float (&acc)[2][4][4]) {
    const int lr = lane & 15;
    const int kh = (lane >> 4) * 16;
    uint32_t ah[2][4], al[2][4], bh[2][4], bl[2][4];
    #pragma unroll
    for (int mt = 0; mt < 2; mt++) {
        int row = m0 + mt * 16 + lr;
        uint32_t off = row * 128 + ((ks * 32 + kh) ^ ((row & 7) << 4));
        ldsm4(bufR + off, ah[mt]);
        ldsm4(bufR + TILE_B + off, al[mt]);
    }
    #pragma unroll
    for (int nt2 = 0; nt2 < 2; nt2++) {
        int row = n0 + nt2 * 16 + lr;
        uint32_t off = row * 128 + ((ks * 32 + kh) ^ ((row & 7) << 4));
        ldsm4(bufR + 2 * TILE_B + off, bh[nt2]);
        ldsm4(bufR + 3 * TILE_B + off, bl[nt2]);
    }
    #pragma unroll
    for (int ps = 0; ps < 3; ps++)
        #pragma unroll
        for (int mt = 0; mt < 2; mt++)
            #pragma unroll
            for (int nt = 0; nt < 4; nt++) {
                int n2 = nt >> 1, sel = nt & 1;
                const uint32_t* A = (ps == 2) ? al[mt] : ah[mt];
                const uint32_t* Bf = (ps == 1) ? bl[n2] : bh[n2];
                mma16816(acc[mt][nt], A, Bf[sel], Bf[sel + 2]);
            }
}

// ---------------- precompute kernels ----------------
__global__ void prep_E(const float* __restrict__ E) {
    __shared__ float s[32][33];
    int b = blockIdx.z;
    int i0 = blockIdx.x * 32, d0 = blockIdx.y * 32;
    int tx = threadIdx.x, ty = threadIdx.y;   // (32, 8)
    #pragma unroll
    for (int q = 0; q < 4; q++) {
        int i = i0 + ty + 8 * q, d = d0 + tx;
        float v = E[((size_t)b * N_ + i) * D_ + d];
        s[ty + 8 * q][tx] = v;
        __half h = __float2half_rn(v);
        __half l = __float2half_rn(v - __half2float(h));
        size_t idx = ((size_t)b * N_ + i) * D_ + d;
        g_ENhi[idx] = h; g_ENlo[idx] = l;
    }
    __syncthreads();
    #pragma unroll
    for (int q = 0; q < 4; q++) {
        int d = d0 + ty + 8 * q, i = i0 + tx;
        float v = s[tx][ty + 8 * q];
        __half h = __float2half_rn(v);
        __half l = __float2half_rn(v - __half2float(h));
        size_t idx = ((size_t)b * D_ + d) * N_ + i;
        g_EThi[idx] = h; g_ETlo[idx] = l;
    }
}

__global__ void prep_W(const float* __restrict__ W) {
    int i = blockIdx.x * 256 + threadIdx.x;
    float v = W[i];
    __half h = __float2half_rn(v);
    g_Whi[i] = h;
    g_Wlo[i] = __float2half_rn(v - __half2float(h));
}

// ---------------- fused main kernel ----------------
__global__ void __launch_bounds__(512, 1)
fused(const float* __restrict__ E, const float* __restrict__ adj,
      const float* __restrict__ cost, const float* __restrict__ W,
      const float* __restrict__ bias, float* __restrict__ out) {
    extern __shared__ char smem[];
    const uint32_t sb = smem_u32(smem);
    float* sDeg = reinterpret_cast<float*>(smem);   // 128 floats, front region

    const int tid = threadIdx.x, w = tid >> 5, l = tid & 31;
    const int wm = w >> 2, wn = w & 3;
    const int m0 = wm * 32, n0 = wn * 32;
    const int b = blockIdx.y, jBase = blockIdx.x * 128;

    const float* Cb = cost + (size_t)b * N_ * N_ + jBase;
    const float* Ab = adj + (size_t)b * N_ * N_ + (size_t)jBase * N_;
    const __half* ETh = g_EThi + (size_t)b * D_ * N_;
    const __half* ETl = g_ETlo + (size_t)b * D_ * N_;

    const int jA  = wn * 32 + l;     // cost tile row (j)
    const int ipb = wm * 8;          // i-pair base
    const int dRow = w * 8 + (l >> 4);
    const int dCol = (l & 15) * 4;

    float acc[2][4][4];
    #pragma unroll
    for (int mt = 0; mt < 2; mt++)
        #pragma unroll
        for (int nt = 0; nt < 4; nt++)
            #pragma unroll
            for (int q = 0; q < 4; q++) acc[mt][nt][q] = 0.f;

    float dacc[4] = {0.f, 0.f, 0.f, 0.f};
    float pa0[8], pa1[8];
    float4 pd[4];

    // ---- prologue ----
    #pragma unroll
    for (int it = 0; it < 8; it++) {
        const float* p = Cb + (size_t)(2 * (ipb + it)) * N_ + jA;
        pa0[it] = p[0]; pa1[it] = p[N_];
    }
    #pragma unroll
    for (int g = 0; g < 4; g++)
        pd[g] = *reinterpret_cast<const float4*>(
            Ab + (size_t)(dRow + 2 * g) * N_ + dCol);
    {   // B chunk 0 -> buf0
        uint32_t bufB = sb + SM_TILES + 2 * TILE_B;
        #pragma unroll
        for (int ks = 0; ks < 4; ks++) {
            int idx = (ks & 1) * 512 + tid;
            int d = idx >> 3, i8 = idx & 7;
            const __half* src = ((ks < 2) ? ETh : ETl) + (size_t)d * N_ + i8 * 8;
            cpasync16(bufB + ((ks < 2) ? 0 : TILE_B) + SWZ(d * 128 + i8 * 16), src);
        }
        CP_COMMIT();
    }
    {   // A chunk 0 convert -> buf0, degree chunk 0
        char* bufW = smem + SM_TILES;
        #pragma unroll
        for (int ks = 0; ks < 4; ks++) {
            int it = 2 * ks;
            uint32_t h0 = cvth2(pa0[it], pa1[it]);
            uint32_t h1 = cvth2(pa0[it + 1], pa1[it + 1]);
            *reinterpret_cast<uint2*>(bufW + SWZ(jA * 128 + (ipb + it) * 4)) =
                make_uint2(h0, h1);
            dacc[ks] += (pd[ks].x + pd[ks].y) + (pd[ks].z + pd[ks].w);
        }
    }
    #pragma unroll
    for (int it = 0; it < 8; it++) {
        const float* p = Cb + (size_t)(KC + 2 * (ipb + it)) * N_ + jA;
        pa0[it] = p[0]; pa1[it] = p[N_];
    }
    #pragma unroll
    for (int g = 0; g < 4; g++)
        pd[g] = *reinterpret_cast<const float4*>(
            Ab + (size_t)(dRow + 2 * g) * N_ + KC + dCol);
    {   // B chunk 1 -> buf1
        uint32_t bufB = sb + SM_TILES + TILE4 + 2 * TILE_B;
        #pragma unroll
        for (int ks = 0; ks < 4; ks++) {
            int idx = (ks & 1) * 512 + tid;
            int d = idx >> 3, i8 = idx & 7;
            const __half* src = ((ks < 2) ? ETh : ETl) + (size_t)d * N_ + KC + i8 * 8;
            cpasync16(bufB + ((ks < 2) ? 0 : TILE_B) + SWZ(d * 128 + i8 * 16), src);
        }
        CP_COMMIT();
    }
    CP_WAIT1();
    __syncthreads();

    // ================= Stage 1 mainloop =================
    // iter c: read buf c%3; A-convert chunk c+1 -> buf (c+1)%3;
    //         LDG A regs + cp.async B for chunk c+2 -> buf (c+2)%3
    for (int c = 0; c < NCH1; c++) {
        const uint32_t bufR = sb + SM_TILES + (c % 3) * TILE4;
        char* bufWc = smem + SM_TILES + ((c + 1) % 3) * TILE4;
        const uint32_t bufB2 = sb + SM_TILES + ((c + 2) % 3) * TILE4 + 2 * TILE_B;
        const bool doConv = (c + 1 < NCH1);
        const bool doLdg  = (c + 2 < NCH1);
        const int k0n = (c + 2) * KC;

        #pragma unroll
        for (int ks = 0; ks < 4; ks++) {
            mma2p(bufR, ks, m0, n0, l, acc);
            if (doConv) {
                int it = 2 * ks;
                uint32_t h0 = cvth2(pa0[it], pa1[it]);
                uint32_t h1 = cvth2(pa0[it + 1], pa1[it + 1]);
                *reinterpret_cast<uint2*>(bufWc + SWZ(jA * 128 + (ipb + it) * 4)) =
                    make_uint2(h0, h1);
                dacc[ks] += (pd[ks].x + pd[ks].y) + (pd[ks].z + pd[ks].w);
            }
            if (doLdg) {
                int it = 2 * ks;
                const float* p = Cb + (size_t)(k0n + 2 * (ipb + it)) * N_ + jA;
                pa0[it] = p[0]; pa1[it] = p[N_];
                const float* p2 = p + 2 * N_;
                pa0[it + 1] = p2[0]; pa1[it + 1] = p2[N_];
                pd[ks] = *reinterpret_cast<const float4*>(
                    Ab + (size_t)(dRow + 2 * ks) * N_ + k0n + dCol);
                int idx = (ks & 1) * 512 + tid;
                int d = idx >> 3, i8 = idx & 7;
                const __half* src =
                    ((ks < 2) ? ETh : ETl) + (size_t)d * N_ + k0n + i8 * 8;
                cpasync16(bufB2 + ((ks < 2) ? 0 : TILE_B) + SWZ(d * 128 + i8 * 16),
                          src);
            }
        }
        if (doLdg) CP_COMMIT();
        if (c >= NCH1 - 2) CP_WAIT0(); else CP_WAIT1();
        __syncthreads();
    }

    // ---- degrees -> smem ----
    #pragma unroll
    for (int t = 0; t < 4; t++) {
        float s = dacc[t];
        s += __shfl_xor_sync(~0u, s, 1);
        s += __shfl_xor_sync(~0u, s, 2);
        s += __shfl_xor_sync(~0u, s, 4);
        s += __shfl_xor_sync(~0u, s, 8);
        if ((l & 15) == 0) sDeg[dRow + 2 * t] = s;
    }
    __syncthreads();

    // ================= Stage 2: out = relu([E|SN] @ W^T + b) ================
    float acc2[2][4][4];
    #pragma unroll
    for (int mt = 0; mt < 2; mt++)
        #pragma unroll
        for (int nt = 0; nt < 4; nt++)
            #pragma unroll
            for (int q = 0; q < 4; q++) acc2[mt][nt][q] = 0.f;

    const __half* ENh = g_ENhi + (size_t)b * N_ * D_;
    const __half* ENl = g_ENlo + (size_t)b * N_ * D_;

    #pragma unroll
    for (int cs = 0; cs < 4; cs++) {
        const int p = (2 + cs) % 3;
        char* bufc = smem + SM_TILES + p * TILE4;
        const uint32_t bufb = sb + SM_TILES + p * TILE4;
        const int s = (cs < 2) ? cs + 2 : cs - 2;   // SN chunks first

        // B2 = W tile [dout][64k]
        #pragma unroll
        for (int q = 0; q < 2; q++) {
            int idx = q * 512 + tid;
            int d = idx >> 3, k8 = idx & 7;
            uint32_t off = SWZ(d * 128 + k8 * 16);
            cpasync16(bufb + 2 * TILE_B + off, g_Whi + d * 256 + s * 64 + k8 * 8);
            cpasync16(bufb + 3 * TILE_B + off, g_Wlo + d * 256 + s * 64 + k8 * 8);
        }
        if (s < 2) {
            // A2 = E rows jBase.., cols 64s..
            #pragma unroll
            for (int q = 0; q < 2; q++) {
                int idx = q * 512 + tid;
                int row = idx >> 3, d8 = idx & 7;
                uint32_t off = SWZ(row * 128 + d8 * 16);
                const size_t srcOff = (size_t)(jBase + row) * D_ + s * 64 + d8 * 8;
                cpasync16(bufb + off, ENh + srcOff);
                cpasync16(bufb + TILE_B + off, ENl + srcOff);
            }
        } else {
            // A2 = SN (hi+lo) from stage-1 accumulators
            if ((wn >> 1) == (s - 2)) {
                #pragma unroll
                for (int mt = 0; mt < 2; mt++) {
                    int r0 = m0 + mt * 16 + (l >> 2);
                    float rd0 = 1.0f / sDeg[r0];
                    float rd1 = 1.0f / sDeg[r0 + 8];
                    #pragma unroll
                    for (int nt = 0; nt < 4; nt++) {
                        int k = (wn & 1) * 32 + nt * 8 + (l & 3) * 2;
                        uint32_t h, lo;
                        split2h(acc[mt][nt][0] * rd0, acc[mt][nt][1] * rd0, h, lo);
                        uint32_t off = SWZ(r0 * 128 + k * 2);
                        *reinterpret_cast<uint32_t*>(bufc + off) = h;
                        *reinterpret_cast<uint32_t*>(bufc + TILE_B + off) = lo;
                        split2h(acc[mt][nt][2] * rd1, acc[mt][nt][3] * rd1, h, lo);
                        off = SWZ((r0 + 8) * 128 + k * 2);
                        *reinterpret_cast<uint32_t*>(bufc + off) = h;
                        *reinterpret_cast<uint32_t*>(bufc + TILE_B + off) = lo;
                    }
                }
            }
        }
        CP_COMMIT();
        CP_WAIT0();
        __syncthreads();
        #pragma unroll
        for (int ks = 0; ks < 4; ks++)
            mma3p(bufb, ks, m0, n0, l, acc2);
        __syncthreads();
    }

    // ---- epilogue: bias + relu + store ----
    #pragma unroll
    for (int mt = 0; mt < 2; mt++)
        #pragma unroll
        for (int nt = 0; nt < 4; nt++) {
            int col = n0 + nt * 8 + (l & 3) * 2;
            float2 bv = *reinterpret_cast<const float2*>(bias + col);
            int r0 = jBase + m0 + mt * 16 + (l >> 2);
            float2 o0, o1;
            o0.x = fmaxf(acc2[mt][nt][0] + bv.x, 0.f);
            o0.y = fmaxf(acc2[mt][nt][1] + bv.y, 0.f);
            o1.x = fmaxf(acc2[mt][nt][2] + bv.x, 0.f);
            o1.y = fmaxf(acc2[mt][nt][3] + bv.y, 0.f);
            *reinterpret_cast<float2*>(
                out + (size_t)b * N_ * D_ + (size_t)r0 * D_ + col) = o0;
            *reinterpret_cast<float2*>(
                out + (size_t)b * N_ * D_ + (size_t)(r0 + 8) * D_ + col) = o1;
        }
}

// ---------------------------------------------------------------------------
extern "C" void kernel_launch(void* const* d_in, const int* in_sizes, int n_in,
                              void* d_out, int out_size) {
    const float* E    = (const float*)d_in[0];
    const float* adj  = (const float*)d_in[1];
    const float* cost = (const float*)d_in[2];
    const float* W    = (const float*)d_in[3];
    const float* bias = (const float*)d_in[4];
    float* out = (float*)d_out;

    {
        dim3 grid(N_ / 32, D_ / 32, B_);
        dim3 blk(32, 8);
        prep_E<<<grid, blk>>>(E);
        prep_W<<<(D_ * 2 * D_) / 256, 256>>>(W);
    }
    cudaFuncSetAttribute(fused, cudaFuncAttributeMaxDynamicSharedMemorySize,
                         SMEM_TOTAL);
    dim3 grid(N_ / 128, B_);
    fused<<<grid, 512, SMEM_TOTAL>>>(E, adj, cost, W, bias, out);
}

// round 9
// speedup vs baseline: 2.2938x; 1.0441x over previous
#include <cuda_runtime.h>
#include <cuda_fp16.h>
#include <cstdint>

#define B_ 8
#define N_ 2048
#define D_ 128
#define KC 64
#define NCH1 32

#define TILE_B 16384
#define TILE4  (4 * TILE_B)
#define SM_TILES 1024
#define NBUF 3
#define SMEM_TOTAL (SM_TILES + NBUF * TILE4)   // 1K + 192K

#define SWZ(x) ((x) ^ (((x) >> 3) & 0x70))

// ---- precomputed fp16 splits (device scratch; no cudaMalloc allowed) ----
__device__ __half g_EThi[B_ * D_ * N_];   // E^T  [b][d][i]   (hi only)
__device__ __half g_ENhi[B_ * N_ * D_];   // E    [b][i][d]
__device__ __half g_ENlo[B_ * N_ * D_];
__device__ __half g_Whi[D_ * 2 * D_];     // W    [dout][k]
__device__ __half g_Wlo[D_ * 2 * D_];

__device__ __forceinline__ uint32_t smem_u32(const void* p) {
    uint32_t a;
    asm("{ .reg .u64 t; cvta.to.shared.u64 t, %1; cvt.u32.u64 %0, t; }"
        : "=r"(a) : "l"(p));
    return a;
}

__device__ __forceinline__ void cpasync16(uint32_t dst, const void* src) {
    asm volatile("cp.async.cg.shared.global [%0], [%1], 16;"
                 :: "r"(dst), "l"(src));
}
#define CP_COMMIT() asm volatile("cp.async.commit_group;" ::: "memory")
#define CP_WAIT0()  asm volatile("cp.async.wait_group 0;" ::: "memory")
#define CP_WAIT1()  asm volatile("cp.async.wait_group 1;" ::: "memory")

// pack 2 floats to fp16x2 (x0 low, x1 high)
__device__ __forceinline__ uint32_t cvth2(float x0, float x1) {
    uint32_t H;
    asm("cvt.rn.f16x2.f32 %0, %1, %2;" : "=r"(H) : "f"(x1), "f"(x0));
    return H;
}
// full split: hi fp16x2 + lo fp16x2
__device__ __forceinline__ void split2h(float x0, float x1,
                                        uint32_t& hi, uint32_t& lo) {
    uint32_t H;
    asm("cvt.rn.f16x2.f32 %0, %1, %2;" : "=r"(H) : "f"(x1), "f"(x0));
    float h0, h1;
    asm("{ .reg .f16 a,b; mov.b32 {a,b}, %2; cvt.f32.f16 %0, a; cvt.f32.f16 %1, b; }"
        : "=f"(h0), "=f"(h1) : "r"(H));
    asm("cvt.rn.f16x2.f32 %0, %1, %2;" : "=r"(lo) : "f"(x1 - h1), "f"(x0 - h0));
    hi = H;
}

__device__ __forceinline__ void ldsm4(uint32_t addr, uint32_t r[4]) {
    asm volatile("ldmatrix.sync.aligned.m8n8.x4.shared.b16 {%0,%1,%2,%3}, [%4];"
                 : "=r"(r[0]), "=r"(r[1]), "=r"(r[2]), "=r"(r[3]) : "r"(addr));
}

__device__ __forceinline__ void mma16816(float c[4],
                                         const uint32_t a[4],
                                         uint32_t b0, uint32_t b1) {
    asm volatile(
        "mma.sync.aligned.m16n8k16.row.col.f32.f16.f16.f32 "
        "{%0,%1,%2,%3}, {%4,%5,%6,%7}, {%8,%9}, {%0,%1,%2,%3};"
        : "+f"(c[0]), "+f"(c[1]), "+f"(c[2]), "+f"(c[3])
        : "r"(a[0]), "r"(a[1]), "r"(a[2]), "r"(a[3]), "r"(b0), "r"(b1));
}

// 1-pass slice (stage 1): acc += Ahi * Bhi
__device__ __forceinline__ void mma1p(uint32_t bufR, int ks, int m0, int n0,
                                      int lane, float (&acc)[2][4][4]) {
    const int lr = lane & 15;
    const int kh = (lane >> 4) * 16;
    uint32_t ah[2][4], bh[2][4];
    #pragma unroll
    for (int mt = 0; mt < 2; mt++) {
        int row = m0 + mt * 16 + lr;
        uint32_t off = row * 128 + ((ks * 32 + kh) ^ ((row & 7) << 4));
        ldsm4(bufR + off, ah[mt]);
    }
    #pragma unroll
    for (int nt2 = 0; nt2 < 2; nt2++) {
        int row = n0 + nt2 * 16 + lr;
        uint32_t off = row * 128 + ((ks * 32 + kh) ^ ((row & 7) << 4));
        ldsm4(bufR + 2 * TILE_B + off, bh[nt2]);
    }
    #pragma unroll
    for (int mt = 0; mt < 2; mt++)
        #pragma unroll
        for (int nt = 0; nt < 4; nt++) {
            int n2 = nt >> 1, sel = nt & 1;
            mma16816(acc[mt][nt], ah[mt], bh[n2][sel], bh[n2][sel + 2]);
        }
}

// 3-pass slice (stage 2): acc += Ahi*Bhi + Ahi*Blo + Alo*Bhi
__device__ __forceinline__ void mma3p(uint32_t bufR, int ks, int m0, int n0,
                                      int lane, float (&acc)[2][4][4]) {
    const int lr = lane & 15;
    const int kh = (lane >> 4) * 16;
    uint32_t ah[2][4], al[2][4], bh[2][4], bl[2][4];
    #pragma unroll
    for (int mt = 0; mt < 2; mt++) {
        int row = m0 + mt * 16 + lr;
        uint32_t off = row * 128 + ((ks * 32 + kh) ^ ((row & 7) << 4));
        ldsm4(bufR + off, ah[mt]);
        ldsm4(bufR + TILE_B + off, al[mt]);
    }
    #pragma unroll
    for (int nt2 = 0; nt2 < 2; nt2++) {
        int row = n0 + nt2 * 16 + lr;
        uint32_t off = row * 128 + ((ks * 32 + kh) ^ ((row & 7) << 4));
        ldsm4(bufR + 2 * TILE_B + off, bh[nt2]);
        ldsm4(bufR + 3 * TILE_B + off, bl[nt2]);
    }
    #pragma unroll
    for (int ps = 0; ps < 3; ps++)
        #pragma unroll
        for (int mt = 0; mt < 2; mt++)
            #pragma unroll
            for (int nt = 0; nt < 4; nt++) {
                int n2 = nt >> 1, sel = nt & 1;
                const uint32_t* A = (ps == 2) ? al[mt] : ah[mt];
                const uint32_t* Bf = (ps == 1) ? bl[n2] : bh[n2];
                mma16816(acc[mt][nt], A, Bf[sel], Bf[sel + 2]);
            }
}

// ---------------- precompute kernels ----------------
__global__ void prep_E(const float* __restrict__ E) {
    __shared__ float s[32][33];
    int b = blockIdx.z;
    int i0 = blockIdx.x * 32, d0 = blockIdx.y * 32;
    int tx = threadIdx.x, ty = threadIdx.y;   // (32, 8)
    #pragma unroll
    for (int q = 0; q < 4; q++) {
        int i = i0 + ty + 8 * q, d = d0 + tx;
        float v = E[((size_t)b * N_ + i) * D_ + d];
        s[ty + 8 * q][tx] = v;
        __half h = __float2half_rn(v);
        __half l = __float2half_rn(v - __half2float(h));
        size_t idx = ((size_t)b * N_ + i) * D_ + d;
        g_ENhi[idx] = h; g_ENlo[idx] = l;
    }
    __syncthreads();
    #pragma unroll
    for (int q = 0; q < 4; q++) {
        int d = d0 + ty + 8 * q, i = i0 + tx;
        float v = s[tx][ty + 8 * q];
        size_t idx = ((size_t)b * D_ + d) * N_ + i;
        g_EThi[idx] = __float2half_rn(v);
    }
}

__global__ void prep_W(const float* __restrict__ W) {
    int i = blockIdx.x * 256 + threadIdx.x;
    float v = W[i];
    __half h = __float2half_rn(v);
    g_Whi[i] = h;
    g_Wlo[i] = __float2half_rn(v - __half2float(h));
}

// ---------------- fused main kernel ----------------
__global__ void __launch_bounds__(512, 1)
fused(const float* __restrict__ E, const float* __restrict__ adj,
      const float* __restrict__ cost, const float* __restrict__ W,
      const float* __restrict__ bias, float* __restrict__ out) {
    extern __shared__ char smem[];
    const uint32_t sb = smem_u32(smem);
    float* sDeg = reinterpret_cast<float*>(smem);   // 128 floats, front region

    const int tid = threadIdx.x, w = tid >> 5, l = tid & 31;
    const int wm = w >> 2, wn = w & 3;
    const int m0 = wm * 32, n0 = wn * 32;
    const int b = blockIdx.y, jBase = blockIdx.x * 128;

    const float* Cb = cost + (size_t)b * N_ * N_ + jBase;
    const float* Ab = adj + (size_t)b * N_ * N_ + (size_t)jBase * N_;
    const __half* ETh = g_EThi + (size_t)b * D_ * N_;

    const int jA  = wn * 32 + l;     // cost tile row (j)
    const int ipb = wm * 8;          // i-pair base
    const int dRow = w * 8 + (l >> 4);
    const int dCol = (l & 15) * 4;

    float acc[2][4][4];
    #pragma unroll
    for (int mt = 0; mt < 2; mt++)
        #pragma unroll
        for (int nt = 0; nt < 4; nt++)
            #pragma unroll
            for (int q = 0; q < 4; q++) acc[mt][nt][q] = 0.f;

    float dacc[4] = {0.f, 0.f, 0.f, 0.f};
    float pa0[8], pa1[8];
    float4 pd[4];

    // ---- prologue ----
    #pragma unroll
    for (int it = 0; it < 8; it++) {
        const float* p = Cb + (size_t)(2 * (ipb + it)) * N_ + jA;
        pa0[it] = p[0]; pa1[it] = p[N_];
    }
    #pragma unroll
    for (int g = 0; g < 4; g++)
        pd[g] = *reinterpret_cast<const float4*>(
            Ab + (size_t)(dRow + 2 * g) * N_ + dCol);
    {   // B chunk 0 (hi only) -> buf0
        uint32_t bufB = sb + SM_TILES + 2 * TILE_B;
        #pragma unroll
        for (int ks = 0; ks < 2; ks++) {
            int idx = ks * 512 + tid;
            int d = idx >> 3, i8 = idx & 7;
            cpasync16(bufB + SWZ(d * 128 + i8 * 16),
                      ETh + (size_t)d * N_ + i8 * 8);
        }
        CP_COMMIT();
    }
    {   // A chunk 0 convert -> buf0, degree chunk 0
        char* bufW = smem + SM_TILES;
        #pragma unroll
        for (int ks = 0; ks < 4; ks++) {
            int it = 2 * ks;
            uint32_t h0 = cvth2(pa0[it], pa1[it]);
            uint32_t h1 = cvth2(pa0[it + 1], pa1[it + 1]);
            *reinterpret_cast<uint2*>(bufW + SWZ(jA * 128 + (ipb + it) * 4)) =
                make_uint2(h0, h1);
            dacc[ks] += (pd[ks].x + pd[ks].y) + (pd[ks].z + pd[ks].w);
        }
    }
    #pragma unroll
    for (int it = 0; it < 8; it++) {
        const float* p = Cb + (size_t)(KC + 2 * (ipb + it)) * N_ + jA;
        pa0[it] = p[0]; pa1[it] = p[N_];
    }
    #pragma unroll
    for (int g = 0; g < 4; g++)
        pd[g] = *reinterpret_cast<const float4*>(
            Ab + (size_t)(dRow + 2 * g) * N_ + KC + dCol);
    {   // B chunk 1 (hi only) -> buf1
        uint32_t bufB = sb + SM_TILES + TILE4 + 2 * TILE_B;
        #pragma unroll
        for (int ks = 0; ks < 2; ks++) {
            int idx = ks * 512 + tid;
            int d = idx >> 3, i8 = idx & 7;
            cpasync16(bufB + SWZ(d * 128 + i8 * 16),
                      ETh + (size_t)d * N_ + KC + i8 * 8);
        }
        CP_COMMIT();
    }
    CP_WAIT1();
    __syncthreads();

    // ================= Stage 1 mainloop (1-pass fp16 hi) =================
    // iter c: read buf c%3; A-convert chunk c+1 -> buf (c+1)%3;
    //         LDG A regs + cp.async B(hi) for chunk c+2 -> buf (c+2)%3
    for (int c = 0; c < NCH1; c++) {
        const uint32_t bufR = sb + SM_TILES + (c % 3) * TILE4;
        char* bufWc = smem + SM_TILES + ((c + 1) % 3) * TILE4;
        const uint32_t bufB2 = sb + SM_TILES + ((c + 2) % 3) * TILE4 + 2 * TILE_B;
        const bool doConv = (c + 1 < NCH1);
        const bool doLdg  = (c + 2 < NCH1);
        const int k0n = (c + 2) * KC;

        #pragma unroll
        for (int ks = 0; ks < 4; ks++) {
            mma1p(bufR, ks, m0, n0, l, acc);
            if (doConv) {
                int it = 2 * ks;
                uint32_t h0 = cvth2(pa0[it], pa1[it]);
                uint32_t h1 = cvth2(pa0[it + 1], pa1[it + 1]);
                *reinterpret_cast<uint2*>(bufWc + SWZ(jA * 128 + (ipb + it) * 4)) =
                    make_uint2(h0, h1);
                dacc[ks] += (pd[ks].x + pd[ks].y) + (pd[ks].z + pd[ks].w);
            }
            if (doLdg) {
                int it = 2 * ks;
                const float* p = Cb + (size_t)(k0n + 2 * (ipb + it)) * N_ + jA;
                pa0[it] = p[0]; pa1[it] = p[N_];
                const float* p2 = p + 2 * N_;
                pa0[it + 1] = p2[0]; pa1[it + 1] = p2[N_];
                pd[ks] = *reinterpret_cast<const float4*>(
                    Ab + (size_t)(dRow + 2 * ks) * N_ + k0n + dCol);
                if (ks < 2) {
                    int idx = ks * 512 + tid;
                    int d = idx >> 3, i8 = idx & 7;
                    cpasync16(bufB2 + SWZ(d * 128 + i8 * 16),
                              ETh + (size_t)d * N_ + k0n + i8 * 8);
                }
            }
        }
        if (doLdg) CP_COMMIT();
        if (c >= NCH1 - 2) CP_WAIT0(); else CP_WAIT1();
        __syncthreads();
    }

    // ---- degrees -> smem ----
    #pragma unroll
    for (int t = 0; t < 4; t++) {
        float s = dacc[t];
        s += __shfl_xor_sync(~0u, s, 1);
        s += __shfl_xor_sync(~0u, s, 2);
        s += __shfl_xor_sync(~0u, s, 4);
        s += __shfl_xor_sync(~0u, s, 8);
        if ((l & 15) == 0) sDeg[dRow + 2 * t] = s;
    }
    __syncthreads();

    // ================= Stage 2: out = relu([E|SN] @ W^T + b) ================
    float acc2[2][4][4];
    #pragma unroll
    for (int mt = 0; mt < 2; mt++)
        #pragma unroll
        for (int nt = 0; nt < 4; nt++)
            #pragma unroll
            for (int q = 0; q < 4; q++) acc2[mt][nt][q] = 0.f;

    const __half* ENh = g_ENhi + (size_t)b * N_ * D_;
    const __half* ENl = g_ENlo + (size_t)b * N_ * D_;

    #pragma unroll
    for (int cs = 0; cs < 4; cs++) {
        const int p = (2 + cs) % 3;
        char* bufc = smem + SM_TILES + p * TILE4;
        const uint32_t bufb = sb + SM_TILES + p * TILE4;
        const int s = (cs < 2) ? cs + 2 : cs - 2;   // SN chunks first

        // B2 = W tile [dout][64k]
        #pragma unroll
        for (int q = 0; q < 2; q++) {
            int idx = q * 512 + tid;
            int d = idx >> 3, k8 = idx & 7;
            uint32_t off = SWZ(d * 128 + k8 * 16);
            cpasync16(bufb + 2 * TILE_B + off, g_Whi + d * 256 + s * 64 + k8 * 8);
            cpasync16(bufb + 3 * TILE_B + off, g_Wlo + d * 256 + s * 64 + k8 * 8);
        }
        if (s < 2) {
            // A2 = E rows jBase.., cols 64s..
            #pragma unroll
            for (int q = 0; q < 2; q++) {
                int idx = q * 512 + tid;
                int row = idx >> 3, d8 = idx & 7;
                uint32_t off = SWZ(row * 128 + d8 * 16);
                const size_t srcOff = (size_t)(jBase + row) * D_ + s * 64 + d8 * 8;
                cpasync16(bufb + off, ENh + srcOff);
                cpasync16(bufb + TILE_B + off, ENl + srcOff);
            }
        } else {
            // A2 = SN (hi+lo) from stage-1 accumulators
            if ((wn >> 1) == (s - 2)) {
                #pragma unroll
                for (int mt = 0; mt < 2; mt++) {
                    int r0 = m0 + mt * 16 + (l >> 2);
                    float rd0 = 1.0f / sDeg[r0];
                    float rd1 = 1.0f / sDeg[r0 + 8];
                    #pragma unroll
                    for (int nt = 0; nt < 4; nt++) {
                        int k = (wn & 1) * 32 + nt * 8 + (l & 3) * 2;
                        uint32_t h, lo;
                        split2h(acc[mt][nt][0] * rd0, acc[mt][nt][1] * rd0, h, lo);
                        uint32_t off = SWZ(r0 * 128 + k * 2);
                        *reinterpret_cast<uint32_t*>(bufc + off) = h;
                        *reinterpret_cast<uint32_t*>(bufc + TILE_B + off) = lo;
                        split2h(acc[mt][nt][2] * rd1, acc[mt][nt][3] * rd1, h, lo);
                        off = SWZ((r0 + 8) * 128 + k * 2);
                        *reinterpret_cast<uint32_t*>(bufc + off) = h;
                        *reinterpret_cast<uint32_t*>(bufc + TILE_B + off) = lo;
                    }
                }
            }
        }
        CP_COMMIT();
        CP_WAIT0();
        __syncthreads();
        #pragma unroll
        for (int ks = 0; ks < 4; ks++)
            mma3p(bufb, ks, m0, n0, l, acc2);
        __syncthreads();
    }

    // ---- epilogue: bias + relu + store ----
    #pragma unroll
    for (int mt = 0; mt < 2; mt++)
        #pragma unroll
        for (int nt = 0; nt < 4; nt++) {
            int col = n0 + nt * 8 + (l & 3) * 2;
            float2 bv = *reinterpret_cast<const float2*>(bias + col);
            int r0 = jBase + m0 + mt * 16 + (l >> 2);
            float2 o0, o1;
            o0.x = fmaxf(acc2[mt][nt][0] + bv.x, 0.f);
            o0.y = fmaxf(acc2[mt][nt][1] + bv.y, 0.f);
            o1.x = fmaxf(acc2[mt][nt][2] + bv.x, 0.f);
            o1.y = fmaxf(acc2[mt][nt][3] + bv.y, 0.f);
            *reinterpret_cast<float2*>(
                out + (size_t)b * N_ * D_ + (size_t)r0 * D_ + col) = o0;
            *reinterpret_cast<float2*>(
                out + (size_t)b * N_ * D_ + (size_t)(r0 + 8) * D_ + col) = o1;
        }
}

// ---------------------------------------------------------------------------
extern "C" void kernel_launch(void* const* d_in, const int* in_sizes, int n_in,
                              void* d_out, int out_size) {
    const float* E    = (const float*)d_in[0];
    const float* adj  = (const float*)d_in[1];
    const float* cost = (const float*)d_in[2];
    const float* W    = (const float*)d_in[3];
    const float* bias = (const float*)d_in[4];
    float* out = (float*)d_out;

    {
        dim3 grid(N_ / 32, D_ / 32, B_);
        dim3 blk(32, 8);
        prep_E<<<grid, blk>>>(E);
        prep_W<<<(D_ * 2 * D_) / 256, 256>>>(W);
    }
    cudaFuncSetAttribute(fused, cudaFuncAttributeMaxDynamicSharedMemorySize,
                         SMEM_TOTAL);
    dim3 grid(N_ / 128, B_);
    fused<<<grid, 512, SMEM_TOTAL>>>(E, adj, cost, W, bias, out);
}

// round 10
// speedup vs baseline: 2.3329x; 1.0171x over previous
#include <cuda_runtime.h>
#include <cuda_fp16.h>
#include <cstdint>

#define B_ 8
#define N_ 2048
#define D_ 128
#define KC 64
#define NCH1 32
#define MT 64                 // M tile (j rows per CTA)

#define CHBUF 24576           // stage-1 buffer: A-hi 8K @0, B-hi 16K @8192
#define OFF_B1 8192
#define SM_TILES 1024
#define SMEM_TOTAL (SM_TILES + 3 * CHBUF)   // 74752 B -> 2 CTAs/SM
// stage-2 layout (single buffer at SM_TILES): AH 0 | AL 8192 | BH 16384 | BL 32768
#define S2_AL 8192
#define S2_BH 16384
#define S2_BL 32768

#define SWZ(x) ((x) ^ (((x) >> 3) & 0x70))

// ---- precomputed fp16 (device scratch; no cudaMalloc allowed) ----
__device__ __half g_EThi[B_ * D_ * N_];   // E^T  [b][d][i]   (hi only)
__device__ __half g_ENhi[B_ * N_ * D_];   // E    [b][i][d]
__device__ __half g_ENlo[B_ * N_ * D_];
__device__ __half g_Whi[D_ * 2 * D_];     // W    [dout][k]
__device__ __half g_Wlo[D_ * 2 * D_];

__device__ __forceinline__ uint32_t smem_u32(const void* p) {
    uint32_t a;
    asm("{ .reg .u64 t; cvta.to.shared.u64 t, %1; cvt.u32.u64 %0, t; }"
        : "=r"(a) : "l"(p));
    return a;
}
__device__ __forceinline__ void cpasync16(uint32_t dst, const void* src) {
    asm volatile("cp.async.cg.shared.global [%0], [%1], 16;"
                 :: "r"(dst), "l"(src));
}
#define CP_COMMIT() asm volatile("cp.async.commit_group;" ::: "memory")
#define CP_WAIT0()  asm volatile("cp.async.wait_group 0;" ::: "memory")
#define CP_WAIT1()  asm volatile("cp.async.wait_group 1;" ::: "memory")

__device__ __forceinline__ uint32_t cvth2(float x0, float x1) {
    uint32_t H;
    asm("cvt.rn.f16x2.f32 %0, %1, %2;" : "=r"(H) : "f"(x1), "f"(x0));
    return H;
}
__device__ __forceinline__ void split2h(float x0, float x1,
                                        uint32_t& hi, uint32_t& lo) {
    uint32_t H;
    asm("cvt.rn.f16x2.f32 %0, %1, %2;" : "=r"(H) : "f"(x1), "f"(x0));
    float h0, h1;
    asm("{ .reg .f16 a,b; mov.b32 {a,b}, %2; cvt.f32.f16 %0, a; cvt.f32.f16 %1, b; }"
        : "=f"(h0), "=f"(h1) : "r"(H));
    asm("cvt.rn.f16x2.f32 %0, %1, %2;" : "=r"(lo) : "f"(x1 - h1), "f"(x0 - h0));
    hi = H;
}

__device__ __forceinline__ void ldsm4(uint32_t addr, uint32_t r[4]) {
    asm volatile("ldmatrix.sync.aligned.m8n8.x4.shared.b16 {%0,%1,%2,%3}, [%4];"
                 : "=r"(r[0]), "=r"(r[1]), "=r"(r[2]), "=r"(r[3]) : "r"(addr));
}
__device__ __forceinline__ void mma16816(float c[4],
                                         const uint32_t a[4],
                                         uint32_t b0, uint32_t b1) {
    asm volatile(
        "mma.sync.aligned.m16n8k16.row.col.f32.f16.f16.f32 "
        "{%0,%1,%2,%3}, {%4,%5,%6,%7}, {%8,%9}, {%0,%1,%2,%3};"
        : "+f"(c[0]), "+f"(c[1]), "+f"(c[2]), "+f"(c[3])
        : "r"(a[0]), "r"(a[1]), "r"(a[2]), "r"(a[3]), "r"(b0), "r"(b1));
}

// stage-1 slice: acc += Ahi * Bhi   (A rows 0..63 @0, B rows 0..127 @OFF_B1)
__device__ __forceinline__ void mma1p(uint32_t bufR, int ks, int m0, int n0,
                                      int lane, float (&acc)[2][4][4]) {
    const int lr = lane & 15;
    const int kh = (lane >> 4) * 16;
    uint32_t ah[2][4], bh[2][4];
    #pragma unroll
    for (int mt = 0; mt < 2; mt++) {
        int row = m0 + mt * 16 + lr;
        uint32_t off = row * 128 + ((ks * 32 + kh) ^ ((row & 7) << 4));
        ldsm4(bufR + off, ah[mt]);
    }
    #pragma unroll
    for (int nt2 = 0; nt2 < 2; nt2++) {
        int row = n0 + nt2 * 16 + lr;
        uint32_t off = row * 128 + ((ks * 32 + kh) ^ ((row & 7) << 4));
        ldsm4(bufR + OFF_B1 + off, bh[nt2]);
    }
    #pragma unroll
    for (int mt = 0; mt < 2; mt++)
        #pragma unroll
        for (int nt = 0; nt < 4; nt++) {
            int n2 = nt >> 1, sel = nt & 1;
            mma16816(acc[mt][nt], ah[mt], bh[n2][sel], bh[n2][sel + 2]);
        }
}

// stage-2 slice: acc += Ahi*Bhi + Ahi*Blo + Alo*Bhi  (S2 layout)
__device__ __forceinline__ void mma3p(uint32_t bufR, int ks, int m0, int n0,
                                      int lane, float (&acc)[2][4][4]) {
    const int lr = lane & 15;
    const int kh = (lane >> 4) * 16;
    uint32_t ah[2][4], al[2][4], bh[2][4], bl[2][4];
    #pragma unroll
    for (int mt = 0; mt < 2; mt++) {
        int row = m0 + mt * 16 + lr;
        uint32_t off = row * 128 + ((ks * 32 + kh) ^ ((row & 7) << 4));
        ldsm4(bufR + off, ah[mt]);
        ldsm4(bufR + S2_AL + off, al[mt]);
    }
    #pragma unroll
    for (int nt2 = 0; nt2 < 2; nt2++) {
        int row = n0 + nt2 * 16 + lr;
        uint32_t off = row * 128 + ((ks * 32 + kh) ^ ((row & 7) << 4));
        ldsm4(bufR + S2_BH + off, bh[nt2]);
        ldsm4(bufR + S2_BL + off, bl[nt2]);
    }
    #pragma unroll
    for (int ps = 0; ps < 3; ps++)
        #pragma unroll
        for (int mt = 0; mt < 2; mt++)
            #pragma unroll
            for (int nt = 0; nt < 4; nt++) {
                int n2 = nt >> 1, sel = nt & 1;
                const uint32_t* A = (ps == 2) ? al[mt] : ah[mt];
                const uint32_t* Bf = (ps == 1) ? bl[n2] : bh[n2];
                mma16816(acc[mt][nt], A, Bf[sel], Bf[sel + 2]);
            }
}

// ---------------- precompute kernels ----------------
__global__ void prep_E(const float* __restrict__ E) {
    __shared__ float s[32][33];
    int b = blockIdx.z;
    int i0 = blockIdx.x * 32, d0 = blockIdx.y * 32;
    int tx = threadIdx.x, ty = threadIdx.y;   // (32, 8)
    #pragma unroll
    for (int q = 0; q < 4; q++) {
        int i = i0 + ty + 8 * q, d = d0 + tx;
        float v = E[((size_t)b * N_ + i) * D_ + d];
        s[ty + 8 * q][tx] = v;
        __half h = __float2half_rn(v);
        __half l = __float2half_rn(v - __half2float(h));
        size_t idx = ((size_t)b * N_ + i) * D_ + d;
        g_ENhi[idx] = h; g_ENlo[idx] = l;
    }
    __syncthreads();
    #pragma unroll
    for (int q = 0; q < 4; q++) {
        int d = d0 + ty + 8 * q, i = i0 + tx;
        size_t idx = ((size_t)b * D_ + d) * N_ + i;
        g_EThi[idx] = __float2half_rn(s[tx][ty + 8 * q]);
    }
}

__global__ void prep_W(const float* __restrict__ W) {
    int i = blockIdx.x * 256 + threadIdx.x;
    float v = W[i];
    __half h = __float2half_rn(v);
    g_Whi[i] = h;
    g_Wlo[i] = __float2half_rn(v - __half2float(h));
}

// ---------------- fused main kernel (M=64, 2 CTAs/SM) ----------------
__global__ void __launch_bounds__(256, 2)
fused(const float* __restrict__ E, const float* __restrict__ adj,
      const float* __restrict__ cost, const float* __restrict__ W,
      const float* __restrict__ bias, float* __restrict__ out) {
    extern __shared__ char smem[];
    const uint32_t sb = smem_u32(smem);
    float* sDeg = reinterpret_cast<float*>(smem);   // 64 floats, front region

    const int tid = threadIdx.x, w = tid >> 5, l = tid & 31;
    const int wm = w >> 2, wn = w & 3;              // wm 0..1, wn 0..3
    const int m0 = wm * 32, n0 = wn * 32;
    const int b = blockIdx.y, jBase = blockIdx.x * MT;

    const float* Cb = cost + (size_t)b * N_ * N_ + jBase;
    const float* Ab = adj + (size_t)b * N_ * N_ + (size_t)jBase * N_;
    const __half* ETh = g_EThi + (size_t)b * D_ * N_;

    const int jA  = (w & 1) * 32 + l;   // cost tile row (j), 0..63
    const int ipb = (w >> 1) * 8;       // i-pair base, 0/8/16/24
    const int dRow = w * 8 + (l >> 4);  // adj row base, 0..57
    const int dCol = (l & 15) * 4;

    float acc[2][4][4];
    #pragma unroll
    for (int mt = 0; mt < 2; mt++)
        #pragma unroll
        for (int nt = 0; nt < 4; nt++)
            #pragma unroll
            for (int q = 0; q < 4; q++) acc[mt][nt][q] = 0.f;

    float dacc[4] = {0.f, 0.f, 0.f, 0.f};
    float pa0[8], pa1[8];
    float4 pd[4];

    // ---- prologue ----
    #pragma unroll
    for (int it = 0; it < 8; it++) {
        const float* p = Cb + (size_t)(2 * (ipb + it)) * N_ + jA;
        pa0[it] = p[0]; pa1[it] = p[N_];
    }
    #pragma unroll
    for (int g = 0; g < 4; g++)
        pd[g] = *reinterpret_cast<const float4*>(
            Ab + (size_t)(dRow + 2 * g) * N_ + dCol);
    {   // B chunk 0 -> buf0
        uint32_t bufB = sb + SM_TILES + OFF_B1;
        #pragma unroll
        for (int q = 0; q < 4; q++) {
            int idx = q * 256 + tid;
            int d = idx >> 3, i8 = idx & 7;
            cpasync16(bufB + SWZ(d * 128 + i8 * 16),
                      ETh + (size_t)d * N_ + i8 * 8);
        }
        CP_COMMIT();
    }
    {   // A chunk 0 convert -> buf0, degree chunk 0
        char* bufW = smem + SM_TILES;
        #pragma unroll
        for (int g = 0; g < 4; g++) {
            int it = 2 * g;
            uint32_t h0 = cvth2(pa0[it], pa1[it]);
            uint32_t h1 = cvth2(pa0[it + 1], pa1[it + 1]);
            *reinterpret_cast<uint2*>(bufW + SWZ(jA * 128 + (ipb + it) * 4)) =
                make_uint2(h0, h1);
            dacc[g] += (pd[g].x + pd[g].y) + (pd[g].z + pd[g].w);
        }
    }
    #pragma unroll
    for (int it = 0; it < 8; it++) {
        const float* p = Cb + (size_t)(KC + 2 * (ipb + it)) * N_ + jA;
        pa0[it] = p[0]; pa1[it] = p[N_];
    }
    #pragma unroll
    for (int g = 0; g < 4; g++)
        pd[g] = *reinterpret_cast<const float4*>(
            Ab + (size_t)(dRow + 2 * g) * N_ + KC + dCol);
    {   // B chunk 1 -> buf1
        uint32_t bufB = sb + SM_TILES + CHBUF + OFF_B1;
        #pragma unroll
        for (int q = 0; q < 4; q++) {
            int idx = q * 256 + tid;
            int d = idx >> 3, i8 = idx & 7;
            cpasync16(bufB + SWZ(d * 128 + i8 * 16),
                      ETh + (size_t)d * N_ + KC + i8 * 8);
        }
        CP_COMMIT();
    }
    CP_WAIT1();
    __syncthreads();

    // ================= Stage 1 mainloop (1-pass fp16 hi) =================
    for (int c = 0; c < NCH1; c++) {
        const uint32_t bufR = sb + SM_TILES + (c % 3) * CHBUF;
        char* bufWc = smem + SM_TILES + ((c + 1) % 3) * CHBUF;
        const uint32_t bufB2 = sb + SM_TILES + ((c + 2) % 3) * CHBUF + OFF_B1;
        const bool doConv = (c + 1 < NCH1);
        const bool doLdg  = (c + 2 < NCH1);
        const int k0n = (c + 2) * KC;

        #pragma unroll
        for (int ks = 0; ks < 4; ks++) {
            mma1p(bufR, ks, m0, n0, l, acc);
            if (doConv) {
                int it = 2 * ks;
                uint32_t h0 = cvth2(pa0[it], pa1[it]);
                uint32_t h1 = cvth2(pa0[it + 1], pa1[it + 1]);
                *reinterpret_cast<uint2*>(bufWc + SWZ(jA * 128 + (ipb + it) * 4)) =
                    make_uint2(h0, h1);
                dacc[ks] += (pd[ks].x + pd[ks].y) + (pd[ks].z + pd[ks].w);
            }
            if (doLdg) {
                int it = 2 * ks;
                const float* p = Cb + (size_t)(k0n + 2 * (ipb + it)) * N_ + jA;
                pa0[it] = p[0]; pa1[it] = p[N_];
                const float* p2 = p + 2 * N_;
                pa0[it + 1] = p2[0]; pa1[it + 1] = p2[N_];
                pd[ks] = *reinterpret_cast<const float4*>(
                    Ab + (size_t)(dRow + 2 * ks) * N_ + k0n + dCol);
                int idx = ks * 256 + tid;
                int d = idx >> 3, i8 = idx & 7;
                cpasync16(bufB2 + SWZ(d * 128 + i8 * 16),
                          ETh + (size_t)d * N_ + k0n + i8 * 8);
            }
        }
        if (doLdg) CP_COMMIT();
        if (c >= NCH1 - 2) CP_WAIT0(); else CP_WAIT1();
        __syncthreads();
    }

    // ---- degrees -> smem ----
    #pragma unroll
    for (int t = 0; t < 4; t++) {
        float s = dacc[t];
        s += __shfl_xor_sync(~0u, s, 1);
        s += __shfl_xor_sync(~0u, s, 2);
        s += __shfl_xor_sync(~0u, s, 4);
        s += __shfl_xor_sync(~0u, s, 8);
        if ((l & 15) == 0) sDeg[dRow + 2 * t] = s;
    }
    __syncthreads();

    // ========= Stage 2: out = relu([E|SN] @ W^T + b), single-buffered ======
    float acc2[2][4][4];
    #pragma unroll
    for (int mt = 0; mt < 2; mt++)
        #pragma unroll
        for (int nt = 0; nt < 4; nt++)
            #pragma unroll
            for (int q = 0; q < 4; q++) acc2[mt][nt][q] = 0.f;

    const __half* ENh = g_ENhi + (size_t)b * N_ * D_;
    const __half* ENl = g_ENlo + (size_t)b * N_ * D_;
    char* S2c = smem + SM_TILES;
    const uint32_t S2b = sb + SM_TILES;

    #pragma unroll
    for (int cs = 0; cs < 4; cs++) {
        const int s = (cs < 2) ? cs + 2 : cs - 2;   // SN chunks first

        // B2 = W tile [dout 128][64 k] hi+lo
        #pragma unroll
        for (int q = 0; q < 4; q++) {
            int idx = q * 256 + tid;
            int d = idx >> 3, k8 = idx & 7;
            uint32_t off = SWZ(d * 128 + k8 * 16);
            cpasync16(S2b + S2_BH + off, g_Whi + d * 256 + s * 64 + k8 * 8);
            cpasync16(S2b + S2_BL + off, g_Wlo + d * 256 + s * 64 + k8 * 8);
        }
        if (s < 2) {
            // A2 = E rows jBase.., cols 64s..
            #pragma unroll
            for (int q = 0; q < 2; q++) {
                int idx = q * 256 + tid;
                int row = idx >> 3, d8 = idx & 7;
                uint32_t off = SWZ(row * 128 + d8 * 16);
                const size_t srcOff = (size_t)(jBase + row) * D_ + s * 64 + d8 * 8;
                cpasync16(S2b + off, ENh + srcOff);
                cpasync16(S2b + S2_AL + off, ENl + srcOff);
            }
        } else {
            // A2 = SN (hi+lo) from stage-1 accumulators
            if ((wn >> 1) == (s - 2)) {
                #pragma unroll
                for (int mt = 0; mt < 2; mt++) {
                    int r0 = m0 + mt * 16 + (l >> 2);
                    float rd0 = 1.0f / sDeg[r0];
                    float rd1 = 1.0f / sDeg[r0 + 8];
                    #pragma unroll
                    for (int nt = 0; nt < 4; nt++) {
                        int k = (wn & 1) * 32 + nt * 8 + (l & 3) * 2;
                        uint32_t h, lo;
                        split2h(acc[mt][nt][0] * rd0, acc[mt][nt][1] * rd0, h, lo);
                        uint32_t off = SWZ(r0 * 128 + k * 2);
                        *reinterpret_cast<uint32_t*>(S2c + off) = h;
                        *reinterpret_cast<uint32_t*>(S2c + S2_AL + off) = lo;
                        split2h(acc[mt][nt][2] * rd1, acc[mt][nt][3] * rd1, h, lo);
                        off = SWZ((r0 + 8) * 128 + k * 2);
                        *reinterpret_cast<uint32_t*>(S2c + off) = h;
                        *reinterpret_cast<uint32_t*>(S2c + S2_AL + off) = lo;
                    }
                }
            }
        }
        CP_COMMIT();
        CP_WAIT0();
        __syncthreads();
        #pragma unroll
        for (int ks = 0; ks < 4; ks++)
            mma3p(S2b, ks, m0, n0, l, acc2);
        __syncthreads();
    }

    // ---- epilogue: bias + relu + store ----
    #pragma unroll
    for (int mt = 0; mt < 2; mt++)
        #pragma unroll
        for (int nt = 0; nt < 4; nt++) {
            int col = n0 + nt * 8 + (l & 3) * 2;
            float2 bv = *reinterpret_cast<const float2*>(bias + col);
            int r0 = jBase + m0 + mt * 16 + (l >> 2);
            float2 o0, o1;
            o0.x = fmaxf(acc2[mt][nt][0] + bv.x, 0.f);
            o0.y = fmaxf(acc2[mt][nt][1] + bv.y, 0.f);
            o1.x = fmaxf(acc2[mt][nt][2] + bv.x, 0.f);
            o1.y = fmaxf(acc2[mt][nt][3] + bv.y, 0.f);
            *reinterpret_cast<float2*>(
                out + (size_t)b * N_ * D_ + (size_t)r0 * D_ + col) = o0;
            *reinterpret_cast<float2*>(
                out + (size_t)b * N_ * D_ + (size_t)(r0 + 8) * D_ + col) = o1;
        }
}

// ---------------------------------------------------------------------------
extern "C" void kernel_launch(void* const* d_in, const int* in_sizes, int n_in,
                              void* d_out, int out_size) {
    const float* E    = (const float*)d_in[0];
    const float* adj  = (const float*)d_in[1];
    const float* cost = (const float*)d_in[2];
    const float* W    = (const float*)d_in[3];
    const float* bias = (const float*)d_in[4];
    float* out = (float*)d_out;

    {
        dim3 grid(N_ / 32, D_ / 32, B_);
        dim3 blk(32, 8);
        prep_E<<<grid, blk>>>(E);
        prep_W<<<(D_ * 2 * D_) / 256, 256>>>(W);
    }
    cudaFuncSetAttribute(fused, cudaFuncAttributeMaxDynamicSharedMemorySize,
                         SMEM_TOTAL);
    dim3 grid(N_ / MT, B_);
    fused<<<grid, 256, SMEM_TOTAL>>>(E, adj, cost, W, bias, out);
}